// round 2
// baseline (speedup 1.0000x reference)
#include <cuda_runtime.h>
#include <math.h>

#define DEV_INLINE __device__ __forceinline__

// ---------------- problem constants ----------------
constexpr int Bc = 2, Nc = 4096, Kc = 32, D0c = 64, D1c = 16, RHc = 16;
constexpr int NN = Bc * Nc;                 // 8192 nodes
constexpr float EPSc = 1e-6f;
constexpr float SCALEc = 0.18898223650461362f;  // 1/sqrt(64/4 + 3*(16/4)) = 1/sqrt(28)

// ---------------- device scratch (no allocs allowed) ----------------
__device__ float g_f0[NN * 64];
__device__ float g_f1[NN * 48];
__device__ float g_g0[NN * 64];
__device__ float g_g1[NN * 48];
__device__ float g_rhat[NN * Kc * 3];
__device__ float g_dist[NN * Kc];

DEV_INLINE float gelu_t(float x) {
    // jax.nn.gelu default (approximate=True, tanh form)
    float x3 = x * x * x;
    return 0.5f * x * (1.0f + tanhf(0.7978845608028654f * (x + 0.044715f * x3)));
}

DEV_INLINE float sigmoidf(float x) { return 1.0f / (1.0f + expf(-x)); }

// ---------------- init: copy inputs into device state ----------------
__global__ void init_kernel(const float* __restrict__ f0, const float* __restrict__ f1) {
    int stride = gridDim.x * blockDim.x;
    for (int i = blockIdx.x * blockDim.x + threadIdx.x; i < NN * 64; i += stride) g_f0[i] = f0[i];
    for (int i = blockIdx.x * blockDim.x + threadIdx.x; i < NN * 48; i += stride) g_f1[i] = f1[i];
}

// ---------------- geometry: rel, dist, rhat (layer-invariant) ----------------
__global__ void geom_kernel(const float* __restrict__ coords, const int* __restrict__ nbr) {
    int idx = blockIdx.x * blockDim.x + threadIdx.x;
    if (idx >= NN * Kc) return;
    int bn = idx / Kc;
    int b = bn / Nc;
    int nb = nbr[idx];
    int gi = b * Nc + nb;
    float dx = coords[gi * 3 + 0] - coords[bn * 3 + 0];
    float dy = coords[gi * 3 + 1] - coords[bn * 3 + 1];
    float dz = coords[gi * 3 + 2] - coords[bn * 3 + 2];
    float d = sqrtf(dx * dx + dy * dy + dz * dz);
    g_dist[idx] = d;
    float inv = 1.0f / (d + EPSc);
    g_rhat[idx * 3 + 0] = dx * inv;
    g_rhat[idx * 3 + 1] = dy * inv;
    g_rhat[idx * 3 + 2] = dz * inv;
}

// ---------------- prenorm: f -> g (LayerNorm on f0, RMS on f1) ----------------
__global__ void prenorm_kernel() {
    int bn = blockIdx.x;
    int t = threadIdx.x;  // 64 threads
    __shared__ float s1[64], s2[64];
    __shared__ float smu, srsig, srms;

    float x = g_f0[bn * 64 + t];
    s1[t] = x;
    s2[t] = x * x;
    __syncthreads();
    for (int o = 32; o > 0; o >>= 1) {
        if (t < o) { s1[t] += s1[t + o]; s2[t] += s2[t + o]; }
        __syncthreads();
    }
    if (t == 0) {
        float mu = s1[0] * (1.0f / 64.0f);
        float var = s2[0] * (1.0f / 64.0f) - mu * mu;
        smu = mu;
        srsig = rsqrtf(var + EPSc);
    }
    __syncthreads();

    float y = (t < 48) ? g_f1[bn * 48 + t] : 0.0f;
    s1[t] = y * y;
    __syncthreads();
    for (int o = 32; o > 0; o >>= 1) {
        if (t < o) s1[t] += s1[t + o];
        __syncthreads();
    }
    if (t == 0) srms = rsqrtf(s1[0] * (1.0f / 16.0f) + EPSc);
    __syncthreads();

    g_g0[bn * 64 + t] = (x - smu) * srsig;
    if (t < 48) g_g1[bn * 48 + t] = y * srms;
}

// ---------------- fused attention kernel ----------------
// block = 256 threads (8 warps), one node per block; each warp handles 4 neighbors.
// shared layout (floats):
constexpr int STG = 1104;          // per-warp stage
constexpr int SH0 = 0;             // h0[q][d]       4*64
constexpr int SH1 = 256;           // h1[q][c][m]    4*48
constexpr int SDOT = 448;          // dot1[q][c]     4*16
constexpr int SRH = 512;           // rh[q][i]       4*16
constexpr int SR1 = 576;           // r1[q][e]       4*16
constexpr int SS01K = 640;         // 4*16
constexpr int SS11K = 704;
constexpr int SS01V = 768;
constexpr int SS11V = 832;
constexpr int SK1 = 896;           // k1[q][t]       4*48
constexpr int SGEO = 1088;         // rx,ry,rz,dist per q  4*4
constexpr int OFF_V0 = 8 * STG;            // 8832  (32*64)
constexpr int OFF_V1 = OFF_V0 + 32 * 64;   // 10880 (32*48)
constexpr int OFF_Q0 = OFF_V1 + 32 * 48;   // 12416 (64)
constexpr int OFF_Q1 = OFF_Q0 + 64;        // 12480 (48)
constexpr int OFF_LOG = OFF_Q1 + 48;       // 12528 (4*32)
constexpr int OFF_O = OFF_LOG + 128;       // 12656 (112)
constexpr int SM_FLOATS = OFF_O + 112;     // 12768
constexpr int SM_BYTES = SM_FLOATS * 4;    // 51072

__global__ void __launch_bounds__(256) attn_kernel(
    const int* __restrict__ nbr,
    const float* __restrict__ Wq0, const float* __restrict__ Wq1,
    const float* __restrict__ Wk00, const float* __restrict__ Wk10,
    const float* __restrict__ Wk01, const float* __restrict__ Wk11, const float* __restrict__ Wk11r,
    const float* __restrict__ Wv00, const float* __restrict__ Wv10,
    const float* __restrict__ Wv01, const float* __restrict__ Wv11, const float* __restrict__ Wv11r,
    const float* __restrict__ Rw1, const float* __restrict__ Rb1,
    const float* __restrict__ Rw20, const float* __restrict__ Rw21,
    const float* __restrict__ Wo0, const float* __restrict__ Wo1)
{
    extern __shared__ float sm[];
    int bn = blockIdx.x;
    int b = bn / Nc;
    int tid = threadIdx.x;
    int wid = tid >> 5;
    int lane = tid & 31;
    float* st = sm + wid * STG;

    // ---- q0 / q1 of self (read g directly; broadcast loads are cheap) ----
    if (tid < 64) {
        float a = 0.0f;
        #pragma unroll 8
        for (int d = 0; d < 64; d++) a += g_g0[bn * 64 + d] * Wq0[d * 64 + tid];
        sm[OFF_Q0 + tid] = a;
    } else if (tid < 112) {
        int t = tid - 64, e = t / 3, m = t - e * 3;
        float a = 0.0f;
        #pragma unroll
        for (int c = 0; c < 16; c++) a += g_g1[bn * 48 + c * 3 + m] * Wq1[c * 16 + e];
        sm[OFF_Q1 + t] = a;
    }

    // ---- stage the warp's 4 neighbors ----
    int j0 = wid * 4;
    #pragma unroll
    for (int q = 0; q < 4; q++) {
        int j = j0 + q;
        int nb = nbr[bn * Kc + j];
        int gi = b * Nc + nb;
        st[SH0 + q * 64 + lane] = g_g0[gi * 64 + lane];
        st[SH0 + q * 64 + 32 + lane] = g_g0[gi * 64 + 32 + lane];
        st[SH1 + q * 48 + lane] = g_g1[gi * 48 + lane];
        if (lane < 16) st[SH1 + q * 48 + 32 + lane] = g_g1[gi * 48 + 32 + lane];
        if (lane == 0) {
            st[SGEO + q * 4 + 0] = g_rhat[(bn * Kc + j) * 3 + 0];
            st[SGEO + q * 4 + 1] = g_rhat[(bn * Kc + j) * 3 + 1];
            st[SGEO + q * 4 + 2] = g_rhat[(bn * Kc + j) * 3 + 2];
            st[SGEO + q * 4 + 3] = g_dist[bn * Kc + j];
        }
    }
    // block sync: orders q0/q1 writes (warps 0-3) before any warp reads them,
    // and makes each warp's staging visible to itself (trivially).
    __syncthreads();

    // ---- dot1 and rh (radial hidden) ----
    #pragma unroll
    for (int u = lane; u < 64; u += 32) {
        int q = u >> 4, c = u & 15;
        const float* h1p = st + SH1 + q * 48 + c * 3;
        st[SDOT + u] = h1p[0] * st[SGEO + q * 4 + 0] + h1p[1] * st[SGEO + q * 4 + 1]
                     + h1p[2] * st[SGEO + q * 4 + 2];
        st[SRH + u] = gelu_t(st[SGEO + q * 4 + 3] * Rw1[c] + Rb1[c]);
    }
    __syncwarp();

    // ---- r1, s01 (h0 @ W01), s11 (dot1 @ W11r); lanes<16 k-side, lanes>=16 v-side ----
    {
        int e = lane & 15;
        bool kside = lane < 16;
        const float* W01 = kside ? Wk01 : Wv01;
        const float* W11r = kside ? Wk11r : Wv11r;
        int o01 = kside ? SS01K : SS01V;
        int o11 = kside ? SS11K : SS11V;
        #pragma unroll
        for (int q = 0; q < 4; q++) {
            float a = 0.0f, bb = 0.0f;
            #pragma unroll 8
            for (int d = 0; d < 64; d++) a += st[SH0 + q * 64 + d] * W01[d * 16 + e];
            #pragma unroll
            for (int c = 0; c < 16; c++) bb += st[SDOT + q * 16 + c] * W11r[c * 16 + e];
            st[o01 + q * 16 + e] = a;
            st[o11 + q * 16 + e] = bb;
        }
        if (kside) {
            #pragma unroll
            for (int q = 0; q < 4; q++) {
                float r = 0.0f;
                #pragma unroll
                for (int i = 0; i < 16; i++) r += st[SRH + q * 16 + i] * Rw21[i * 16 + e];
                st[SR1 + q * 16 + e] = r;
            }
        }
    }
    __syncwarp();

    // ---- main k0/v0 GEMM: lane handles channels c=lane and c=lane+32, 4 neighbors ----
    float k0a[4] = {0, 0, 0, 0}, k0b[4] = {0, 0, 0, 0};
    float v0a[4] = {0, 0, 0, 0}, v0b[4] = {0, 0, 0, 0};
    #pragma unroll 4
    for (int d = 0; d < 64; d++) {
        float wka = Wk00[d * 64 + lane], wkb = Wk00[d * 64 + 32 + lane];
        float wva = Wv00[d * 64 + lane], wvb = Wv00[d * 64 + 32 + lane];
        #pragma unroll
        for (int q = 0; q < 4; q++) {
            float h = st[SH0 + q * 64 + d];
            k0a[q] += h * wka; k0b[q] += h * wkb;
            v0a[q] += h * wva; v0b[q] += h * wvb;
        }
    }
    #pragma unroll
    for (int e = 0; e < 16; e++) {
        float wka = Wk10[e * 64 + lane], wkb = Wk10[e * 64 + 32 + lane];
        float wva = Wv10[e * 64 + lane], wvb = Wv10[e * 64 + 32 + lane];
        #pragma unroll
        for (int q = 0; q < 4; q++) {
            float dd = st[SDOT + q * 16 + e];
            k0a[q] += dd * wka; k0b[q] += dd * wkb;
            v0a[q] += dd * wva; v0b[q] += dd * wvb;
        }
    }
    // r0 (radial scale for degree-0)
    float r0a[4] = {0, 0, 0, 0}, r0b[4] = {0, 0, 0, 0};
    #pragma unroll
    for (int i = 0; i < 16; i++) {
        float wa = Rw20[i * 64 + lane], wb = Rw20[i * 64 + 32 + lane];
        #pragma unroll
        for (int q = 0; q < 4; q++) {
            float rv = st[SRH + q * 16 + i];
            r0a[q] += rv * wa; r0b[q] += rv * wb;
        }
    }
    #pragma unroll
    for (int q = 0; q < 4; q++) {
        k0a[q] *= r0a[q]; k0b[q] *= r0b[q];
        v0a[q] *= r0a[q]; v0b[q] *= r0b[q];
        sm[OFF_V0 + (j0 + q) * 64 + lane] = v0a[q];
        sm[OFF_V0 + (j0 + q) * 64 + 32 + lane] = v0b[q];
    }

    // ---- degree-0 logit partials via 16-lane-group shuffle reduction ----
    {
        float la[4], lb[4];
        #pragma unroll
        for (int q = 0; q < 4; q++) {
            la[q] = sm[OFF_Q0 + lane] * k0a[q];
            lb[q] = sm[OFF_Q0 + 32 + lane] * k0b[q];
        }
        #pragma unroll
        for (int o = 8; o > 0; o >>= 1) {
            #pragma unroll
            for (int q = 0; q < 4; q++) {
                la[q] += __shfl_xor_sync(0xffffffffu, la[q], o);
                lb[q] += __shfl_xor_sync(0xffffffffu, lb[q], o);
            }
        }
        if (lane == 0) {
            #pragma unroll
            for (int q = 0; q < 4; q++) {
                sm[OFF_LOG + 0 * 32 + j0 + q] = la[q];  // head 0 (c 0..15)
                sm[OFF_LOG + 2 * 32 + j0 + q] = lb[q];  // head 2 (c 32..47)
            }
        }
        if (lane == 16) {
            #pragma unroll
            for (int q = 0; q < 4; q++) {
                sm[OFF_LOG + 1 * 32 + j0 + q] = la[q];  // head 1
                sm[OFF_LOG + 3 * 32 + j0 + q] = lb[q];  // head 3
            }
        }
    }

    // ---- k1/v1 (degree-1): 4*48 outputs over 32 lanes ----
    #pragma unroll
    for (int u = lane; u < 192; u += 32) {
        int q = u / 48, t = u - q * 48;
        int e = t / 3, m = t - e * 3;
        float rm = st[SGEO + q * 4 + m];
        float r1e = st[SR1 + q * 16 + e];
        float hk = (st[SS01K + q * 16 + e] + st[SS11K + q * 16 + e]) * rm;
        float hv = (st[SS01V + q * 16 + e] + st[SS11V + q * 16 + e]) * rm;
        #pragma unroll
        for (int c = 0; c < 16; c++) {
            float hh = st[SH1 + q * 48 + c * 3 + m];
            hk += hh * Wk11[c * 16 + e];
            hv += hh * Wv11[c * 16 + e];
        }
        st[SK1 + q * 48 + t] = hk * r1e;
        sm[OFF_V1 + (j0 + q) * 48 + t] = hv * r1e;
    }
    __syncwarp();

    // ---- final logits: add degree-1 contribution, scale ----
    if (lane < 4) {
        int h = lane;
        #pragma unroll
        for (int q = 0; q < 4; q++) {
            float lg = 0.0f;
            #pragma unroll
            for (int t = 0; t < 12; t++)
                lg += sm[OFF_Q1 + h * 12 + t] * st[SK1 + q * 48 + h * 12 + t];
            int j = j0 + q;
            sm[OFF_LOG + h * 32 + j] = (sm[OFF_LOG + h * 32 + j] + lg) * SCALEc;
        }
    }
    __syncthreads();

    // ---- softmax over neighbors (warp 0, lane = neighbor) ----
    if (tid < 32) {
        #pragma unroll
        for (int h = 0; h < 4; h++) {
            float x = sm[OFF_LOG + h * 32 + tid];
            float mx = x;
            #pragma unroll
            for (int o = 16; o > 0; o >>= 1) mx = fmaxf(mx, __shfl_xor_sync(0xffffffffu, mx, o));
            float ev = expf(x - mx);
            float s = ev;
            #pragma unroll
            for (int o = 16; o > 0; o >>= 1) s += __shfl_xor_sync(0xffffffffu, s, o);
            sm[OFF_LOG + h * 32 + tid] = ev / s;
        }
    }
    __syncthreads();

    // ---- weighted sum over neighbors ----
    if (tid < 112) {
        int h = (tid < 64) ? (tid >> 4) : ((tid - 64) / 12);
        float acc = 0.0f;
        #pragma unroll 8
        for (int j = 0; j < 32; j++) {
            float v = (tid < 64) ? sm[OFF_V0 + j * 64 + tid] : sm[OFF_V1 + j * 48 + (tid - 64)];
            acc += sm[OFF_LOG + h * 32 + j] * v;
        }
        sm[OFF_O + tid] = acc;
    }
    __syncthreads();

    // ---- output projection + residual ----
    if (tid < 64) {
        float a = 0.0f;
        #pragma unroll 8
        for (int d = 0; d < 64; d++) a += sm[OFF_O + d] * Wo0[d * 64 + tid];
        g_f0[bn * 64 + tid] += a;
    } else if (tid < 112) {
        int t = tid - 64, e = t / 3, m = t - e * 3;
        float a = 0.0f;
        #pragma unroll
        for (int c = 0; c < 16; c++) a += sm[OFF_O + 64 + c * 3 + m] * Wo1[c * 16 + e];
        g_f1[bn * 48 + t] += a;
    }
}

// ---------------- fused feed-forward (per node) ----------------
__global__ void __launch_bounds__(256) ff_kernel(
    const float* __restrict__ F0w1, const float* __restrict__ F0w2,
    const float* __restrict__ F1w1, const float* __restrict__ F1w2)
{
    int bn = blockIdx.x;
    int tid = threadIdx.x;
    __shared__ float sf[112], sg[112], sh[256], su[192];
    __shared__ float smu, srsig, srms;

    if (tid < 112) sf[tid] = (tid < 64) ? g_f0[bn * 64 + tid] : g_f1[bn * 48 + tid - 64];
    __syncthreads();

    if (tid < 32) {
        float a = sf[tid] + sf[tid + 32];
        float b2 = sf[tid] * sf[tid] + sf[tid + 32] * sf[tid + 32];
        float c2 = sf[64 + tid] * sf[64 + tid] + ((tid < 16) ? sf[96 + tid] * sf[96 + tid] : 0.0f);
        #pragma unroll
        for (int o = 16; o > 0; o >>= 1) {
            a += __shfl_xor_sync(0xffffffffu, a, o);
            b2 += __shfl_xor_sync(0xffffffffu, b2, o);
            c2 += __shfl_xor_sync(0xffffffffu, c2, o);
        }
        if (tid == 0) {
            float mu = a * (1.0f / 64.0f);
            smu = mu;
            srsig = rsqrtf(b2 * (1.0f / 64.0f) - mu * mu + EPSc);
            srms = rsqrtf(c2 * (1.0f / 16.0f) + EPSc);
        }
    }
    __syncthreads();
    if (tid < 112) sg[tid] = (tid < 64) ? (sf[tid] - smu) * srsig : sf[tid] * srms;
    __syncthreads();

    // hidden 256 = gelu(g0 @ F0w1)
    {
        float a = 0.0f;
        #pragma unroll 8
        for (int d = 0; d < 64; d++) a += sg[d] * F0w1[d * 256 + tid];
        sh[tid] = gelu_t(a);
    }
    // u1 (64 channels x 3 comps) = g1 @ F1w1
    if (tid < 192) {
        int e = tid / 3, m = tid - e * 3;
        float a = 0.0f;
        #pragma unroll
        for (int c = 0; c < 16; c++) a += sg[64 + c * 3 + m] * F1w1[c * 64 + e];
        su[tid] = a;
    }
    __syncthreads();
    if (tid < 64) {
        float u0 = su[tid * 3], u1 = su[tid * 3 + 1], u2 = su[tid * 3 + 2];
        float gate = sigmoidf(sqrtf(u0 * u0 + u1 * u1 + u2 * u2));
        su[tid * 3] = u0 * gate;
        su[tid * 3 + 1] = u1 * gate;
        su[tid * 3 + 2] = u2 * gate;
    }
    __syncthreads();
    if (tid < 64) {
        float a = 0.0f;
        #pragma unroll 8
        for (int i = 0; i < 256; i++) a += sh[i] * F0w2[i * 64 + tid];
        g_f0[bn * 64 + tid] = sf[tid] + a;
    } else if (tid < 112) {
        int t = tid - 64, f = t / 3, m = t - f * 3;
        float a = 0.0f;
        #pragma unroll 8
        for (int e = 0; e < 64; e++) a += su[e * 3 + m] * F1w2[e * 16 + f];
        g_f1[bn * 48 + t] = sf[tid] + a;
    }
}

// ---------------- concat to output ----------------
__global__ void concat_kernel(float* __restrict__ out) {
    int i = blockIdx.x * blockDim.x + threadIdx.x;
    if (i >= NN * 112) return;
    int bn = i / 112, c = i - bn * 112;
    out[i] = (c < 64) ? g_f0[bn * 64 + c] : g_f1[bn * 48 + (c - 64)];
}

// ---------------- launch ----------------
extern "C" void kernel_launch(void* const* d_in, const int* in_sizes, int n_in,
                              void* d_out, int out_size) {
    const float* f0 = (const float*)d_in[0];
    const float* f1 = (const float*)d_in[1];
    const float* coords = (const float*)d_in[2];
    const int* nbr = (const int*)d_in[3];
    const float* Wq0 = (const float*)d_in[4];
    const float* Wq1 = (const float*)d_in[5];
    const float* Wk00 = (const float*)d_in[6];
    const float* Wk10 = (const float*)d_in[7];
    const float* Wk01 = (const float*)d_in[8];
    const float* Wk11 = (const float*)d_in[9];
    const float* Wk11r = (const float*)d_in[10];
    const float* Wv00 = (const float*)d_in[11];
    const float* Wv10 = (const float*)d_in[12];
    const float* Wv01 = (const float*)d_in[13];
    const float* Wv11 = (const float*)d_in[14];
    const float* Wv11r = (const float*)d_in[15];
    const float* Rw1 = (const float*)d_in[16];
    const float* Rb1 = (const float*)d_in[17];
    const float* Rw20 = (const float*)d_in[18];
    const float* Rw21 = (const float*)d_in[19];
    const float* Wo0 = (const float*)d_in[20];
    const float* Wo1 = (const float*)d_in[21];
    const float* F0w1 = (const float*)d_in[22];
    const float* F0w2 = (const float*)d_in[23];
    const float* F1w1 = (const float*)d_in[24];
    const float* F1w2 = (const float*)d_in[25];
    float* out = (float*)d_out;

    cudaFuncSetAttribute(attn_kernel, cudaFuncAttributeMaxDynamicSharedMemorySize, SM_BYTES);

    init_kernel<<<512, 256>>>(f0, f1);
    geom_kernel<<<(NN * Kc + 255) / 256, 256>>>(coords, nbr);

    for (int l = 0; l < 2; l++) {
        prenorm_kernel<<<NN, 64>>>();
        attn_kernel<<<NN, 256, SM_BYTES>>>(
            nbr,
            Wq0 + l * 64 * 64, Wq1 + l * 16 * 16,
            Wk00 + l * 64 * 64, Wk10 + l * 16 * 64,
            Wk01 + l * 64 * 16, Wk11 + l * 16 * 16, Wk11r + l * 16 * 16,
            Wv00 + l * 64 * 64, Wv10 + l * 16 * 64,
            Wv01 + l * 64 * 16, Wv11 + l * 16 * 16, Wv11r + l * 16 * 16,
            Rw1 + l * 16, Rb1 + l * 16,
            Rw20 + l * 16 * 64, Rw21 + l * 16 * 16,
            Wo0 + l * 64 * 64, Wo1 + l * 16 * 16);
        ff_kernel<<<NN, 256>>>(
            F0w1 + l * 64 * 256, F0w2 + l * 256 * 64,
            F1w1 + l * 16 * 64, F1w2 + l * 64 * 16);
    }
    concat_kernel<<<(NN * 112 + 255) / 256, 256>>>(out);
}

// round 5
// speedup vs baseline: 1.2797x; 1.2797x over previous
#include <cuda_runtime.h>
#include <math.h>

#define DEV_INLINE __device__ __forceinline__

// ---------------- problem constants ----------------
constexpr int Bc = 2, Nc = 4096, Kc = 32;
constexpr int NN = Bc * Nc;                 // 8192 nodes
constexpr float EPSc = 1e-6f;
constexpr float SCALEc = 0.18898223650461362f;  // 1/sqrt(64/4 + 3*(16/4)) = 1/sqrt(28)

// ---------------- device scratch (no allocs allowed) ----------------
__device__ float g_f0[NN * 64];
__device__ float g_f1[NN * 48];
__device__ float g_g0[NN * 64];
__device__ float g_g1[NN * 48];
__device__ float g_rhat[NN * Kc * 3];
__device__ float g_dist[NN * Kc];

DEV_INLINE float gelu_t(float x) {
    float x3 = x * x * x;
    return 0.5f * x * (1.0f + tanhf(0.7978845608028654f * (x + 0.044715f * x3)));
}
DEV_INLINE float sigmoidf(float x) { return 1.0f / (1.0f + expf(-x)); }

// ---------------- init + first prenorm (fused) ----------------
__global__ void init_prenorm_kernel(const float* __restrict__ f0in, const float* __restrict__ f1in) {
    int bn = blockIdx.x;
    int t = threadIdx.x;  // 64 threads
    __shared__ float s1[64], s2[64];
    __shared__ float smu, srsig, srms;

    float x = f0in[bn * 64 + t];
    g_f0[bn * 64 + t] = x;
    float y = (t < 48) ? f1in[bn * 48 + t] : 0.0f;
    if (t < 48) g_f1[bn * 48 + t] = y;

    s1[t] = x; s2[t] = x * x;
    __syncthreads();
    for (int o = 32; o > 0; o >>= 1) {
        if (t < o) { s1[t] += s1[t + o]; s2[t] += s2[t + o]; }
        __syncthreads();
    }
    if (t == 0) {
        float mu = s1[0] * (1.0f / 64.0f);
        smu = mu;
        srsig = rsqrtf(s2[0] * (1.0f / 64.0f) - mu * mu + EPSc);
    }
    __syncthreads();
    s1[t] = y * y;
    __syncthreads();
    for (int o = 32; o > 0; o >>= 1) {
        if (t < o) s1[t] += s1[t + o];
        __syncthreads();
    }
    if (t == 0) srms = rsqrtf(s1[0] * (1.0f / 16.0f) + EPSc);
    __syncthreads();

    g_g0[bn * 64 + t] = (x - smu) * srsig;
    if (t < 48) g_g1[bn * 48 + t] = y * srms;
}

// ---------------- geometry ----------------
__global__ void geom_kernel(const float* __restrict__ coords, const int* __restrict__ nbr) {
    int idx = blockIdx.x * blockDim.x + threadIdx.x;
    if (idx >= NN * Kc) return;
    int bn = idx / Kc;
    int b = bn / Nc;
    int gi = b * Nc + nbr[idx];
    float dx = coords[gi * 3 + 0] - coords[bn * 3 + 0];
    float dy = coords[gi * 3 + 1] - coords[bn * 3 + 1];
    float dz = coords[gi * 3 + 2] - coords[bn * 3 + 2];
    float d = sqrtf(dx * dx + dy * dy + dz * dz);
    g_dist[idx] = d;
    float inv = 1.0f / (d + EPSc);
    g_rhat[idx * 3 + 0] = dx * inv;
    g_rhat[idx * 3 + 1] = dy * inv;
    g_rhat[idx * 3 + 2] = dz * inv;
}

// ---------------- fused attention kernel ----------------
// block = 256 threads (8 warps), one node per block.
// Block-shared staging of all 32 neighbors; warps split K/V, 8 neighbors each.
constexpr int BH0 = 0;        // h0[j][d]        32*64
constexpr int BH1 = 2048;     // h1[j][t]        32*48
constexpr int BGEO = 3584;    // [j][rx,ry,rz,d] 32*4
constexpr int BDOT = 3712;    // dot1[j][c]      32*16
constexpr int BRH = 4224;     // rh[j][i]        32*16
constexpr int BR1 = 4736;     // r1[j][e]        32*16
constexpr int BS01 = 5248;    // [side][j][e]    2*32*16
constexpr int BS11 = 6272;    // [side][j][e]    2*32*16
constexpr int BK1 = 7296;     // k1[j][t]        32*48
constexpr int BV1 = 8832;     // v1[j][t]        32*48
constexpr int BV0 = 10368;    // v0[j][d]        32*64
constexpr int BQ0 = 12416;    // 64
constexpr int BQ1 = 12480;    // 48
constexpr int BLOG = 12528;   // 4*32
constexpr int BO = 12656;     // 112
constexpr int SM_FLOATS = 12768;
constexpr int SM_BYTES = SM_FLOATS * 4;  // 51072

__global__ void __launch_bounds__(256, 3) attn_kernel(
    const int* __restrict__ nbr,
    const float* __restrict__ Wq0, const float* __restrict__ Wq1,
    const float* __restrict__ Wk00, const float* __restrict__ Wk10,
    const float* __restrict__ Wk01, const float* __restrict__ Wk11, const float* __restrict__ Wk11r,
    const float* __restrict__ Wv00, const float* __restrict__ Wv10,
    const float* __restrict__ Wv01, const float* __restrict__ Wv11, const float* __restrict__ Wv11r,
    const float* __restrict__ Rw1, const float* __restrict__ Rb1,
    const float* __restrict__ Rw20, const float* __restrict__ Rw21,
    const float* __restrict__ Wo0, const float* __restrict__ Wo1)
{
    extern __shared__ float sm[];
    int bn = blockIdx.x;
    int b = bn >> 12;  // Nc = 4096
    int tid = threadIdx.x;
    int wid = tid >> 5;
    int lane = tid & 31;

    // ---- P0: q0/q1 of self + stage 32 neighbors (warp w stages j=4w..4w+3) ----
    if (tid < 64) {
        float a = 0.0f;
        #pragma unroll 8
        for (int d = 0; d < 64; d++) a += g_g0[bn * 64 + d] * Wq0[d * 64 + tid];
        sm[BQ0 + tid] = a;
    } else if (tid < 112) {
        int t = tid - 64, e = t / 3, m = t - e * 3;
        float a = 0.0f;
        #pragma unroll
        for (int c = 0; c < 16; c++) a += g_g1[bn * 48 + c * 3 + m] * Wq1[c * 16 + e];
        sm[BQ1 + t] = a;
    }
    {
        int jb = wid * 4;
        int js[4];
        #pragma unroll
        for (int q = 0; q < 4; q++) js[q] = nbr[bn * Kc + jb + q];
        #pragma unroll
        for (int u = lane; u < 64; u += 32) {
            int q = u >> 4, v = u & 15;
            int gi = b * Nc + js[q];
            ((float4*)(sm + BH0))[(jb + q) * 16 + v] = ((const float4*)g_g0)[gi * 16 + v];
        }
        #pragma unroll
        for (int u = lane; u < 48; u += 32) {
            int q = u / 12, v = u - q * 12;
            int gi = b * Nc + js[q];
            ((float4*)(sm + BH1))[(jb + q) * 12 + v] = ((const float4*)g_g1)[gi * 12 + v];
        }
        if (lane < 16) {
            int q = lane >> 2, comp = lane & 3;
            int e = bn * Kc + jb + q;
            sm[BGEO + (jb + q) * 4 + comp] = (comp < 3) ? g_rhat[e * 3 + comp] : g_dist[e];
        }
    }
    __syncthreads();

    // ---- P1: dot1[j][c], rh[j][c] (block-wide, 512 items each) ----
    #pragma unroll
    for (int u = tid; u < 512; u += 256) {
        int j = u >> 4, c = u & 15;
        const float* h1p = sm + BH1 + j * 48 + c * 3;
        const float* gp = sm + BGEO + j * 4;
        sm[BDOT + u] = h1p[0] * gp[0] + h1p[1] * gp[1] + h1p[2] * gp[2];
        sm[BRH + u] = gelu_t(gp[3] * Rw1[c] + Rb1[c]);
    }
    __syncthreads();

    // ---- P2: s01 = h0@W01, s11 = dot1@W11r (both sides), r1 = rh@Rw21 ----
    {
        int side = tid >> 7;       // 0=K, 1=V
        int j = (tid >> 2) & 31;
        int e4 = tid & 3;
        const float* W01 = side ? Wv01 : Wk01;
        const float* W11r = side ? Wv11r : Wk11r;

        float4 acc = {0, 0, 0, 0};
        const float4* h0v = (const float4*)(sm + BH0 + j * 64);
        #pragma unroll 4
        for (int d4 = 0; d4 < 16; d4++) {
            float4 h = h0v[d4];
            #pragma unroll
            for (int dd = 0; dd < 4; dd++) {
                float hv = ((const float*)&h)[dd];
                float4 w = ((const float4*)(W01 + (d4 * 4 + dd) * 16))[e4];
                acc.x += hv * w.x; acc.y += hv * w.y; acc.z += hv * w.z; acc.w += hv * w.w;
            }
        }
        ((float4*)(sm + BS01))[side * 128 + j * 4 + e4] = acc;

        float4 a2 = {0, 0, 0, 0};
        const float* dt = sm + BDOT + j * 16;
        #pragma unroll
        for (int c = 0; c < 16; c++) {
            float dv = dt[c];
            float4 w = ((const float4*)(W11r + c * 16))[e4];
            a2.x += dv * w.x; a2.y += dv * w.y; a2.z += dv * w.z; a2.w += dv * w.w;
        }
        ((float4*)(sm + BS11))[side * 128 + j * 4 + e4] = a2;

        if (side == 0) {
            float4 r = {0, 0, 0, 0};
            const float* rh = sm + BRH + j * 16;
            #pragma unroll
            for (int i = 0; i < 16; i++) {
                float rv = rh[i];
                float4 w = ((const float4*)(Rw21 + i * 16))[e4];
                r.x += rv * w.x; r.y += rv * w.y; r.z += rv * w.z; r.w += rv * w.w;
            }
            ((float4*)(sm + BR1))[j * 4 + e4] = r;
        }
    }
    __syncthreads();

    // ---- P3: main k0/v0 GEMM — warp = (side, 8 neighbors) ----
    {
        int side = wid & 1;        // even warps: K, odd: V
        int jb = (wid >> 1) * 8;
        const float* W00 = side ? Wv00 : Wk00;
        const float* W10 = side ? Wv10 : Wk10;

        float a[8] = {0, 0, 0, 0, 0, 0, 0, 0};
        float bb[8] = {0, 0, 0, 0, 0, 0, 0, 0};
        #pragma unroll 2
        for (int d4 = 0; d4 < 16; d4++) {
            float4 h[8];
            #pragma unroll
            for (int q = 0; q < 8; q++) h[q] = ((const float4*)(sm + BH0 + (jb + q) * 64))[d4];
            #pragma unroll
            for (int dd = 0; dd < 4; dd++) {
                float wa = W00[(d4 * 4 + dd) * 64 + lane];
                float wb = W00[(d4 * 4 + dd) * 64 + 32 + lane];
                #pragma unroll
                for (int q = 0; q < 8; q++) {
                    float hv = ((const float*)&h[q])[dd];
                    a[q] += hv * wa; bb[q] += hv * wb;
                }
            }
        }
        #pragma unroll
        for (int e4 = 0; e4 < 4; e4++) {
            float4 h[8];
            #pragma unroll
            for (int q = 0; q < 8; q++) h[q] = ((const float4*)(sm + BDOT + (jb + q) * 16))[e4];
            #pragma unroll
            for (int ee = 0; ee < 4; ee++) {
                float wa = W10[(e4 * 4 + ee) * 64 + lane];
                float wb = W10[(e4 * 4 + ee) * 64 + 32 + lane];
                #pragma unroll
                for (int q = 0; q < 8; q++) {
                    float hv = ((const float*)&h[q])[ee];
                    a[q] += hv * wa; bb[q] += hv * wb;
                }
            }
        }
        // r0 = rh @ Rw20
        float r0a[8] = {0, 0, 0, 0, 0, 0, 0, 0};
        float r0b[8] = {0, 0, 0, 0, 0, 0, 0, 0};
        #pragma unroll
        for (int e4 = 0; e4 < 4; e4++) {
            float4 h[8];
            #pragma unroll
            for (int q = 0; q < 8; q++) h[q] = ((const float4*)(sm + BRH + (jb + q) * 16))[e4];
            #pragma unroll
            for (int ee = 0; ee < 4; ee++) {
                float wa = Rw20[(e4 * 4 + ee) * 64 + lane];
                float wb = Rw20[(e4 * 4 + ee) * 64 + 32 + lane];
                #pragma unroll
                for (int q = 0; q < 8; q++) {
                    float hv = ((const float*)&h[q])[ee];
                    r0a[q] += hv * wa; r0b[q] += hv * wb;
                }
            }
        }
        #pragma unroll
        for (int q = 0; q < 8; q++) { a[q] *= r0a[q]; bb[q] *= r0b[q]; }

        if (side) {
            #pragma unroll
            for (int q = 0; q < 8; q++) {
                sm[BV0 + (jb + q) * 64 + lane] = a[q];
                sm[BV0 + (jb + q) * 64 + 32 + lane] = bb[q];
            }
        } else {
            float q0a = sm[BQ0 + lane], q0b = sm[BQ0 + 32 + lane];
            float la[8], lb[8];
            #pragma unroll
            for (int q = 0; q < 8; q++) { la[q] = q0a * a[q]; lb[q] = q0b * bb[q]; }
            #pragma unroll
            for (int o = 8; o > 0; o >>= 1) {
                #pragma unroll
                for (int q = 0; q < 8; q++) {
                    la[q] += __shfl_xor_sync(0xffffffffu, la[q], o);
                    lb[q] += __shfl_xor_sync(0xffffffffu, lb[q], o);
                }
            }
            if (lane == 0) {
                #pragma unroll
                for (int q = 0; q < 8; q++) {
                    sm[BLOG + 0 * 32 + jb + q] = la[q];  // head 0
                    sm[BLOG + 2 * 32 + jb + q] = lb[q];  // head 2
                }
            }
            if (lane == 16) {
                #pragma unroll
                for (int q = 0; q < 8; q++) {
                    sm[BLOG + 1 * 32 + jb + q] = la[q];  // head 1
                    sm[BLOG + 3 * 32 + jb + q] = lb[q];  // head 3
                }
            }
        }
    }

    // ---- P4: k1/v1 assembly (768 items: side x j x m x e4), 3 per thread ----
    #pragma unroll
    for (int r = 0; r < 3; r++) {
        int item = r * 256 + tid;
        int side = (item >= 384) ? 1 : 0;
        int rem = item - side * 384;
        int j = rem / 12, sub = rem - j * 12;
        int m = sub >> 2, e4 = sub & 3;
        const float* W11 = side ? Wv11 : Wk11;

        float4 acc = {0, 0, 0, 0};
        const float* h1p = sm + BH1 + j * 48 + m;
        #pragma unroll
        for (int c = 0; c < 16; c++) {
            float hv = h1p[c * 3];
            float4 w = ((const float4*)(W11 + c * 16))[e4];
            acc.x += hv * w.x; acc.y += hv * w.y; acc.z += hv * w.z; acc.w += hv * w.w;
        }
        float rm = sm[BGEO + j * 4 + m];
        float* out = sm + (side ? BV1 : BK1) + j * 48;
        const float* s01 = sm + BS01 + side * 512 + j * 16;
        const float* s11 = sm + BS11 + side * 512 + j * 16;
        const float* r1 = sm + BR1 + j * 16;
        #pragma unroll
        for (int i = 0; i < 4; i++) {
            int e = e4 * 4 + i;
            float val = (((const float*)&acc)[i] + (s01[e] + s11[e]) * rm) * r1[e];
            out[e * 3 + m] = val;
        }
    }
    __syncthreads();

    // ---- P5: finalize logits with degree-1 term ----
    if (tid < 128) {
        int h = tid & 3, j = tid >> 2;
        float lg = 0.0f;
        #pragma unroll
        for (int t = 0; t < 12; t++)
            lg += sm[BQ1 + h * 12 + t] * sm[BK1 + j * 48 + h * 12 + t];
        sm[BLOG + h * 32 + j] = (sm[BLOG + h * 32 + j] + lg) * SCALEc;
    }
    __syncthreads();

    // ---- P6: softmax over neighbors ----
    if (tid < 32) {
        #pragma unroll
        for (int h = 0; h < 4; h++) {
            float x = sm[BLOG + h * 32 + tid];
            float mx = x;
            #pragma unroll
            for (int o = 16; o > 0; o >>= 1) mx = fmaxf(mx, __shfl_xor_sync(0xffffffffu, mx, o));
            float ev = expf(x - mx);
            float s = ev;
            #pragma unroll
            for (int o = 16; o > 0; o >>= 1) s += __shfl_xor_sync(0xffffffffu, s, o);
            sm[BLOG + h * 32 + tid] = ev / s;
        }
    }
    __syncthreads();

    // ---- P7: weighted sum over neighbors ----
    if (tid < 112) {
        int h = (tid < 64) ? (tid >> 4) : ((tid - 64) / 12);
        float acc = 0.0f;
        #pragma unroll 8
        for (int j = 0; j < 32; j++) {
            float v = (tid < 64) ? sm[BV0 + j * 64 + tid] : sm[BV1 + j * 48 + (tid - 64)];
            acc += sm[BLOG + h * 32 + j] * v;
        }
        sm[BO + tid] = acc;
    }
    __syncthreads();

    // ---- P8: output projection + residual ----
    if (tid < 64) {
        float a = 0.0f;
        #pragma unroll 8
        for (int d = 0; d < 64; d++) a += sm[BO + d] * Wo0[d * 64 + tid];
        g_f0[bn * 64 + tid] += a;
    } else if (tid < 112) {
        int t = tid - 64, e = t / 3, m = t - e * 3;
        float a = 0.0f;
        #pragma unroll
        for (int c = 0; c < 16; c++) a += sm[BO + 64 + c * 3 + m] * Wo1[c * 16 + e];
        g_f1[bn * 48 + t] += a;
    }
}

// ---------------- fused feed-forward (+ next-layer prenorm) ----------------
__global__ void __launch_bounds__(256) ff_kernel(
    const float* __restrict__ F0w1, const float* __restrict__ F0w2,
    const float* __restrict__ F1w1, const float* __restrict__ F1w2)
{
    int bn = blockIdx.x;
    int tid = threadIdx.x;
    __shared__ float sf[112], sg[112], sh[256], su[192];
    __shared__ float smu, srsig, srms;

    if (tid < 112) sf[tid] = (tid < 64) ? g_f0[bn * 64 + tid] : g_f1[bn * 48 + tid - 64];
    __syncthreads();

    if (tid < 32) {
        float a = sf[tid] + sf[tid + 32];
        float b2 = sf[tid] * sf[tid] + sf[tid + 32] * sf[tid + 32];
        float c2 = sf[64 + tid] * sf[64 + tid] + ((tid < 16) ? sf[96 + tid] * sf[96 + tid] : 0.0f);
        #pragma unroll
        for (int o = 16; o > 0; o >>= 1) {
            a += __shfl_xor_sync(0xffffffffu, a, o);
            b2 += __shfl_xor_sync(0xffffffffu, b2, o);
            c2 += __shfl_xor_sync(0xffffffffu, c2, o);
        }
        if (tid == 0) {
            float mu = a * (1.0f / 64.0f);
            smu = mu;
            srsig = rsqrtf(b2 * (1.0f / 64.0f) - mu * mu + EPSc);
            srms = rsqrtf(c2 * (1.0f / 16.0f) + EPSc);
        }
    }
    __syncthreads();
    if (tid < 112) sg[tid] = (tid < 64) ? (sf[tid] - smu) * srsig : sf[tid] * srms;
    __syncthreads();

    // hidden 256 = gelu(g0 @ F0w1)
    {
        float a = 0.0f;
        #pragma unroll 8
        for (int d = 0; d < 64; d++) a += sg[d] * F0w1[d * 256 + tid];
        sh[tid] = gelu_t(a);
    }
    // u1 (64 ch x 3 comps) = g1 @ F1w1
    if (tid < 192) {
        int e = tid / 3, m = tid - e * 3;
        float a = 0.0f;
        #pragma unroll
        for (int c = 0; c < 16; c++) a += sg[64 + c * 3 + m] * F1w1[c * 64 + e];
        su[tid] = a;
    }
    __syncthreads();
    if (tid < 64) {
        float u0 = su[tid * 3], u1 = su[tid * 3 + 1], u2 = su[tid * 3 + 2];
        float gate = sigmoidf(sqrtf(u0 * u0 + u1 * u1 + u2 * u2));
        su[tid * 3] = u0 * gate;
        su[tid * 3 + 1] = u1 * gate;
        su[tid * 3 + 2] = u2 * gate;
    }
    __syncthreads();

    float newv = 0.0f;
    if (tid < 64) {
        float a = 0.0f;
        #pragma unroll 8
        for (int i = 0; i < 256; i++) a += sh[i] * F0w2[i * 64 + tid];
        newv = sf[tid] + a;
    } else if (tid < 112) {
        int t = tid - 64, f = t / 3, m = t - f * 3;
        float a = 0.0f;
        #pragma unroll 8
        for (int e = 0; e < 64; e++) a += su[e * 3 + m] * F1w2[e * 16 + f];
        newv = sf[tid] + a;
    }
    __syncthreads();  // all reads of sh/su done before overwrite
    if (tid < 112) {
        sh[tid] = newv;
        if (tid < 64) g_f0[bn * 64 + tid] = newv; else g_f1[bn * 48 + tid - 64] = newv;
    }
    __syncthreads();

    // ---- next-layer prenorm on new f ----
    if (tid < 32) {
        float a = sh[tid] + sh[tid + 32];
        float b2 = sh[tid] * sh[tid] + sh[tid + 32] * sh[tid + 32];
        float c2 = sh[64 + tid] * sh[64 + tid] + ((tid < 16) ? sh[96 + tid] * sh[96 + tid] : 0.0f);
        #pragma unroll
        for (int o = 16; o > 0; o >>= 1) {
            a += __shfl_xor_sync(0xffffffffu, a, o);
            b2 += __shfl_xor_sync(0xffffffffu, b2, o);
            c2 += __shfl_xor_sync(0xffffffffu, c2, o);
        }
        if (tid == 0) {
            float mu = a * (1.0f / 64.0f);
            smu = mu;
            srsig = rsqrtf(b2 * (1.0f / 64.0f) - mu * mu + EPSc);
            srms = rsqrtf(c2 * (1.0f / 16.0f) + EPSc);
        }
    }
    __syncthreads();
    if (tid < 64) g_g0[bn * 64 + tid] = (sh[tid] - smu) * srsig;
    else if (tid < 112) g_g1[bn * 48 + tid - 64] = sh[tid] * srms;
}

// ---------------- concat to output ----------------
__global__ void concat_kernel(float* __restrict__ out) {
    int i = blockIdx.x * blockDim.x + threadIdx.x;
    if (i >= NN * 112) return;
    int bn = i / 112, c = i - bn * 112;
    out[i] = (c < 64) ? g_f0[bn * 64 + c] : g_f1[bn * 48 + (c - 64)];
}

// ---------------- launch ----------------
extern "C" void kernel_launch(void* const* d_in, const int* in_sizes, int n_in,
                              void* d_out, int out_size) {
    const float* f0 = (const float*)d_in[0];
    const float* f1 = (const float*)d_in[1];
    const float* coords = (const float*)d_in[2];
    const int* nbr = (const int*)d_in[3];
    const float* Wq0 = (const float*)d_in[4];
    const float* Wq1 = (const float*)d_in[5];
    const float* Wk00 = (const float*)d_in[6];
    const float* Wk10 = (const float*)d_in[7];
    const float* Wk01 = (const float*)d_in[8];
    const float* Wk11 = (const float*)d_in[9];
    const float* Wk11r = (const float*)d_in[10];
    const float* Wv00 = (const float*)d_in[11];
    const float* Wv10 = (const float*)d_in[12];
    const float* Wv01 = (const float*)d_in[13];
    const float* Wv11 = (const float*)d_in[14];
    const float* Wv11r = (const float*)d_in[15];
    const float* Rw1 = (const float*)d_in[16];
    const float* Rb1 = (const float*)d_in[17];
    const float* Rw20 = (const float*)d_in[18];
    const float* Rw21 = (const float*)d_in[19];
    const float* Wo0 = (const float*)d_in[20];
    const float* Wo1 = (const float*)d_in[21];
    const float* F0w1 = (const float*)d_in[22];
    const float* F0w2 = (const float*)d_in[23];
    const float* F1w1 = (const float*)d_in[24];
    const float* F1w2 = (const float*)d_in[25];
    float* out = (float*)d_out;

    cudaFuncSetAttribute(attn_kernel, cudaFuncAttributeMaxDynamicSharedMemorySize, SM_BYTES);

    init_prenorm_kernel<<<NN, 64>>>(f0, f1);
    geom_kernel<<<(NN * Kc + 255) / 256, 256>>>(coords, nbr);

    for (int l = 0; l < 2; l++) {
        attn_kernel<<<NN, 256, SM_BYTES>>>(
            nbr,
            Wq0 + l * 64 * 64, Wq1 + l * 16 * 16,
            Wk00 + l * 64 * 64, Wk10 + l * 16 * 64,
            Wk01 + l * 64 * 16, Wk11 + l * 16 * 16, Wk11r + l * 16 * 16,
            Wv00 + l * 64 * 64, Wv10 + l * 16 * 64,
            Wv01 + l * 64 * 16, Wv11 + l * 16 * 16, Wv11r + l * 16 * 16,
            Rw1 + l * 16, Rb1 + l * 16,
            Rw20 + l * 16 * 64, Rw21 + l * 16 * 16,
            Wo0 + l * 64 * 64, Wo1 + l * 16 * 16);
        ff_kernel<<<NN, 256>>>(
            F0w1 + l * 64 * 256, F0w2 + l * 256 * 64,
            F1w1 + l * 16 * 64, F1w2 + l * 64 * 16);
    }
    concat_kernel<<<(NN * 112 + 255) / 256, 256>>>(out);
}

// round 6
// speedup vs baseline: 1.5368x; 1.2008x over previous
#include <cuda_runtime.h>
#include <math.h>

#define DEV_INLINE __device__ __forceinline__

// ---------------- problem constants ----------------
constexpr int Bc = 2, Nc = 4096, Kc = 32, NB = 8;
constexpr int NN = Bc * Nc;                 // 8192 nodes
constexpr float EPSc = 1e-6f;
constexpr float SCALEc = 0.18898223650461362f;  // 1/sqrt(28)

// ---------------- device scratch ----------------
__device__ float g_f0[NN * 64];
__device__ float g_f1[NN * 48];
__device__ float g_g0[NN * 64];
__device__ float g_g1[NN * 48];
__device__ float g_q0[NN * 64];
__device__ float g_q1[NN * 48];
__device__ float g_rhat[NN * Kc * 3];
__device__ float g_dist[NN * Kc];

DEV_INLINE float tanh_fast(float z) {
    z = fminf(fmaxf(z, -10.0f), 10.0f);
    float e = __expf(2.0f * z);
    return __fdividef(e - 1.0f, e + 1.0f);
}
DEV_INLINE float gelu_t(float x) {
    float x3 = x * x * x;
    return 0.5f * x * (1.0f + tanh_fast(0.7978845608028654f * (x + 0.044715f * x3)));
}
DEV_INLINE float sigmoid_f(float x) { return __fdividef(1.0f, 1.0f + __expf(-x)); }

// ---------------- geometry ----------------
__global__ void geom_kernel(const float* __restrict__ coords, const int* __restrict__ nbr) {
    int idx = blockIdx.x * blockDim.x + threadIdx.x;
    if (idx >= NN * Kc) return;
    int bn = idx / Kc;
    int b = bn / Nc;
    int gi = b * Nc + nbr[idx];
    float dx = coords[gi * 3 + 0] - coords[bn * 3 + 0];
    float dy = coords[gi * 3 + 1] - coords[bn * 3 + 1];
    float dz = coords[gi * 3 + 2] - coords[bn * 3 + 2];
    float d = sqrtf(dx * dx + dy * dy + dz * dz);
    g_dist[idx] = d;
    float inv = 1.0f / (d + EPSc);
    g_rhat[idx * 3 + 0] = dx * inv;
    g_rhat[idx * 3 + 1] = dy * inv;
    g_rhat[idx * 3 + 2] = dz * inv;
}

// ---------------- init: copy f, prenorm, q0/q1 for layer 0 (8 nodes/block) ----------------
__global__ void __launch_bounds__(256) prenorm_q_init_kernel(
    const float* __restrict__ f0in, const float* __restrict__ f1in,
    const float* __restrict__ Wq0, const float* __restrict__ Wq1)
{
    __shared__ __align__(16) float sf0[NB * 64], sf1[NB * 48];
    __shared__ __align__(16) float sg0[NB * 64], sg1[NB * 48];
    __shared__ __align__(16) float sp[4 * NB * 64];
    int nd0 = blockIdx.x * NB;
    int tid = threadIdx.x, wid = tid >> 5, lane = tid & 31;

    if (tid < 128) {
        float4 v = ((const float4*)(f0in + nd0 * 64))[tid];
        ((float4*)sf0)[tid] = v;
        ((float4*)(g_f0 + nd0 * 64))[tid] = v;
    } else {
        int t = tid - 128;
        if (t < 96) {
            float4 v = ((const float4*)(f1in + nd0 * 48))[t];
            ((float4*)sf1)[t] = v;
            ((float4*)(g_f1 + nd0 * 48))[t] = v;
        }
    }
    __syncthreads();

    // prenorm: warp per node
    {
        int nd = wid;
        float x0 = sf0[nd * 64 + lane], x1 = sf0[nd * 64 + 32 + lane];
        float y0 = sf1[nd * 48 + lane], y1 = (lane < 16) ? sf1[nd * 48 + 32 + lane] : 0.0f;
        float s = x0 + x1, s2 = x0 * x0 + x1 * x1, c2 = y0 * y0 + y1 * y1;
        #pragma unroll
        for (int o = 16; o > 0; o >>= 1) {
            s += __shfl_xor_sync(0xffffffffu, s, o);
            s2 += __shfl_xor_sync(0xffffffffu, s2, o);
            c2 += __shfl_xor_sync(0xffffffffu, c2, o);
        }
        float mu = s * (1.0f / 64.0f);
        float rsig = rsqrtf(s2 * (1.0f / 64.0f) - mu * mu + EPSc);
        float rms = rsqrtf(c2 * (1.0f / 16.0f) + EPSc);
        float a0 = (x0 - mu) * rsig, a1 = (x1 - mu) * rsig;
        sg0[nd * 64 + lane] = a0; sg0[nd * 64 + 32 + lane] = a1;
        g_g0[(nd0 + nd) * 64 + lane] = a0; g_g0[(nd0 + nd) * 64 + 32 + lane] = a1;
        float b0 = y0 * rms;
        sg1[nd * 48 + lane] = b0; g_g1[(nd0 + nd) * 48 + lane] = b0;
        if (lane < 16) {
            float b1 = y1 * rms;
            sg1[nd * 48 + 32 + lane] = b1; g_g1[(nd0 + nd) * 48 + 32 + lane] = b1;
        }
    }
    __syncthreads();

    // q0 = g0 @ Wq0 (chunked over d)
    {
        int col = tid & 63, chunk = tid >> 6;
        float acc[NB] = {0, 0, 0, 0, 0, 0, 0, 0};
        #pragma unroll
        for (int d4 = 0; d4 < 4; d4++) {
            float4 g[NB];
            #pragma unroll
            for (int nd = 0; nd < NB; nd++) g[nd] = ((const float4*)(sg0 + nd * 64))[chunk * 4 + d4];
            #pragma unroll
            for (int dd = 0; dd < 4; dd++) {
                float w = Wq0[(chunk * 16 + d4 * 4 + dd) * 64 + col];
                #pragma unroll
                for (int nd = 0; nd < NB; nd++) acc[nd] += ((const float*)&g[nd])[dd] * w;
            }
        }
        #pragma unroll
        for (int nd = 0; nd < NB; nd++) sp[(chunk * NB + nd) * 64 + col] = acc[nd];
    }
    __syncthreads();
    #pragma unroll
    for (int r = 0; r < 2; r++) {
        int o = r * 256 + tid;
        int nd = o >> 6, col = o & 63;
        float v = sp[nd * 64 + col] + sp[(NB + nd) * 64 + col]
                + sp[(2 * NB + nd) * 64 + col] + sp[(3 * NB + nd) * 64 + col];
        g_q0[(nd0 + nd) * 64 + col] = v;
    }
    // q1 = einsum(g1, Wq1)
    if (tid < 128) {
        int nd = tid >> 4, e = tid & 15;
        float a0 = 0, a1 = 0, a2 = 0;
        #pragma unroll
        for (int c = 0; c < 16; c++) {
            float w = Wq1[c * 16 + e];
            a0 += sg1[nd * 48 + c * 3 + 0] * w;
            a1 += sg1[nd * 48 + c * 3 + 1] * w;
            a2 += sg1[nd * 48 + c * 3 + 2] * w;
        }
        g_q1[(nd0 + nd) * 48 + e * 3 + 0] = a0;
        g_q1[(nd0 + nd) * 48 + e * 3 + 1] = a1;
        g_q1[(nd0 + nd) * 48 + e * 3 + 2] = a2;
    }
}

// ---------------- fused attention kernel ----------------
constexpr int BH0 = 0;        // h0[j][d]        32*64
constexpr int BH1 = 2048;     // h1[j][t]        32*48
constexpr int BGEO = 3584;    // [j][rx,ry,rz,d] 32*4
constexpr int BDOT = 3712;    // dot1[j][c]      32*16
constexpr int BRH = 4224;     // rh[j][i]        32*16
constexpr int BR1 = 4736;     // r1[j][e]        32*16
constexpr int BS01 = 5248;    // [side][j][e]    2*32*16
constexpr int BS11 = 6272;    // [side][j][e]    2*32*16
constexpr int BK1 = 7296;     // k1[j][t]        32*48
constexpr int BV1 = 8832;     // v1[j][t]        32*48
constexpr int BV0 = 10368;    // v0[j][d]        32*64
constexpr int BQ0 = 12416;    // 64
constexpr int BQ1 = 12480;    // 48
constexpr int BLOG = 12528;   // 4*32
constexpr int BO = 12656;     // 112
constexpr int SM_FLOATS = 12768;
constexpr int SM_BYTES = SM_FLOATS * 4;  // 51072

__global__ void __launch_bounds__(256, 3) attn_kernel(
    const int* __restrict__ nbr,
    const float* __restrict__ Wk00, const float* __restrict__ Wk10,
    const float* __restrict__ Wk01, const float* __restrict__ Wk11, const float* __restrict__ Wk11r,
    const float* __restrict__ Wv00, const float* __restrict__ Wv10,
    const float* __restrict__ Wv01, const float* __restrict__ Wv11, const float* __restrict__ Wv11r,
    const float* __restrict__ Rw1, const float* __restrict__ Rb1,
    const float* __restrict__ Rw20, const float* __restrict__ Rw21,
    const float* __restrict__ Wo0, const float* __restrict__ Wo1)
{
    extern __shared__ float sm[];
    int bn = blockIdx.x;
    int b = bn >> 12;  // Nc = 4096
    int tid = threadIdx.x;
    int wid = tid >> 5;
    int lane = tid & 31;

    // ---- P0: load precomputed q0/q1 + stage 32 neighbors ----
    if (tid < 16) {
        ((float4*)(sm + BQ0))[tid] = ((const float4*)(g_q0 + bn * 64))[tid];
    } else if (tid < 28) {
        ((float4*)(sm + BQ1))[tid - 16] = ((const float4*)(g_q1 + bn * 48))[tid - 16];
    }
    {
        int jb = wid * 4;
        int js[4];
        #pragma unroll
        for (int q = 0; q < 4; q++) js[q] = nbr[bn * Kc + jb + q];
        #pragma unroll
        for (int u = lane; u < 64; u += 32) {
            int q = u >> 4, v = u & 15;
            int gi = b * Nc + js[q];
            ((float4*)(sm + BH0))[(jb + q) * 16 + v] = ((const float4*)g_g0)[gi * 16 + v];
        }
        #pragma unroll
        for (int u = lane; u < 48; u += 32) {
            int q = u / 12, v = u - q * 12;
            int gi = b * Nc + js[q];
            ((float4*)(sm + BH1))[(jb + q) * 12 + v] = ((const float4*)g_g1)[gi * 12 + v];
        }
        if (lane < 16) {
            int q = lane >> 2, comp = lane & 3;
            int e = bn * Kc + jb + q;
            sm[BGEO + (jb + q) * 4 + comp] = (comp < 3) ? g_rhat[e * 3 + comp] : g_dist[e];
        }
    }
    __syncthreads();

    // ---- P1: dot1[j][c], rh[j][c] ----
    #pragma unroll
    for (int u = tid; u < 512; u += 256) {
        int j = u >> 4, c = u & 15;
        const float* h1p = sm + BH1 + j * 48 + c * 3;
        const float* gp = sm + BGEO + j * 4;
        sm[BDOT + u] = h1p[0] * gp[0] + h1p[1] * gp[1] + h1p[2] * gp[2];
        sm[BRH + u] = gelu_t(gp[3] * Rw1[c] + Rb1[c]);
    }
    __syncthreads();

    // ---- P2: s01 = h0@W01, s11 = dot1@W11r, r1 = rh@Rw21 ----
    {
        int side = tid >> 7;       // 0=K, 1=V
        int j = (tid >> 2) & 31;
        int e4 = tid & 3;
        const float* W01 = side ? Wv01 : Wk01;
        const float* W11r = side ? Wv11r : Wk11r;

        float4 acc = {0, 0, 0, 0};
        const float4* h0v = (const float4*)(sm + BH0 + j * 64);
        #pragma unroll 4
        for (int d4 = 0; d4 < 16; d4++) {
            float4 h = h0v[d4];
            #pragma unroll
            for (int dd = 0; dd < 4; dd++) {
                float hv = ((const float*)&h)[dd];
                float4 w = ((const float4*)(W01 + (d4 * 4 + dd) * 16))[e4];
                acc.x += hv * w.x; acc.y += hv * w.y; acc.z += hv * w.z; acc.w += hv * w.w;
            }
        }
        ((float4*)(sm + BS01))[side * 128 + j * 4 + e4] = acc;

        float4 a2 = {0, 0, 0, 0};
        const float* dt = sm + BDOT + j * 16;
        #pragma unroll
        for (int c = 0; c < 16; c++) {
            float dv = dt[c];
            float4 w = ((const float4*)(W11r + c * 16))[e4];
            a2.x += dv * w.x; a2.y += dv * w.y; a2.z += dv * w.z; a2.w += dv * w.w;
        }
        ((float4*)(sm + BS11))[side * 128 + j * 4 + e4] = a2;

        if (side == 0) {
            float4 r = {0, 0, 0, 0};
            const float* rh = sm + BRH + j * 16;
            #pragma unroll
            for (int i = 0; i < 16; i++) {
                float rv = rh[i];
                float4 w = ((const float4*)(Rw21 + i * 16))[e4];
                r.x += rv * w.x; r.y += rv * w.y; r.z += rv * w.z; r.w += rv * w.w;
            }
            ((float4*)(sm + BR1))[j * 4 + e4] = r;
        }
    }
    __syncthreads();

    // ---- P3: main k0/v0 GEMM — warp = (side, 8 neighbors), channels (2*lane, 2*lane+1) ----
    {
        int side = wid & 1;
        int jb = (wid >> 1) * 8;
        const float* W00 = side ? Wv00 : Wk00;
        const float* W10 = side ? Wv10 : Wk10;
        int c0 = lane * 2;

        float a[8] = {0, 0, 0, 0, 0, 0, 0, 0};
        float bb[8] = {0, 0, 0, 0, 0, 0, 0, 0};
        #pragma unroll 2
        for (int d4 = 0; d4 < 16; d4++) {
            float4 h[8];
            #pragma unroll
            for (int q = 0; q < 8; q++) h[q] = ((const float4*)(sm + BH0 + (jb + q) * 64))[d4];
            #pragma unroll
            for (int dd = 0; dd < 4; dd++) {
                float2 w = *(const float2*)(W00 + (d4 * 4 + dd) * 64 + c0);
                #pragma unroll
                for (int q = 0; q < 8; q++) {
                    float hv = ((const float*)&h[q])[dd];
                    a[q] += hv * w.x; bb[q] += hv * w.y;
                }
            }
        }
        #pragma unroll
        for (int e4 = 0; e4 < 4; e4++) {
            float4 h[8];
            #pragma unroll
            for (int q = 0; q < 8; q++) h[q] = ((const float4*)(sm + BDOT + (jb + q) * 16))[e4];
            #pragma unroll
            for (int ee = 0; ee < 4; ee++) {
                float2 w = *(const float2*)(W10 + (e4 * 4 + ee) * 64 + c0);
                #pragma unroll
                for (int q = 0; q < 8; q++) {
                    float hv = ((const float*)&h[q])[ee];
                    a[q] += hv * w.x; bb[q] += hv * w.y;
                }
            }
        }
        float r0a[8] = {0, 0, 0, 0, 0, 0, 0, 0};
        float r0b[8] = {0, 0, 0, 0, 0, 0, 0, 0};
        #pragma unroll
        for (int e4 = 0; e4 < 4; e4++) {
            float4 h[8];
            #pragma unroll
            for (int q = 0; q < 8; q++) h[q] = ((const float4*)(sm + BRH + (jb + q) * 16))[e4];
            #pragma unroll
            for (int ee = 0; ee < 4; ee++) {
                float2 w = *(const float2*)(Rw20 + (e4 * 4 + ee) * 64 + c0);
                #pragma unroll
                for (int q = 0; q < 8; q++) {
                    float hv = ((const float*)&h[q])[ee];
                    r0a[q] += hv * w.x; r0b[q] += hv * w.y;
                }
            }
        }
        #pragma unroll
        for (int q = 0; q < 8; q++) { a[q] *= r0a[q]; bb[q] *= r0b[q]; }

        if (side) {
            #pragma unroll
            for (int q = 0; q < 8; q++)
                *(float2*)(sm + BV0 + (jb + q) * 64 + c0) = make_float2(a[q], bb[q]);
        } else {
            float2 q0p = *(const float2*)(sm + BQ0 + c0);
            float la[8];
            #pragma unroll
            for (int q = 0; q < 8; q++) la[q] = q0p.x * a[q] + q0p.y * bb[q];
            #pragma unroll
            for (int o = 4; o > 0; o >>= 1) {
                #pragma unroll
                for (int q = 0; q < 8; q++)
                    la[q] += __shfl_xor_sync(0xffffffffu, la[q], o);
            }
            if ((lane & 7) == 0) {
                int h = lane >> 3;  // head = channel/16, channels 16h..16h+15 live in lanes 8h..8h+7
                #pragma unroll
                for (int q = 0; q < 8; q++) sm[BLOG + h * 32 + jb + q] = la[q];
            }
        }
    }

    // ---- P4: k1/v1 assembly ----
    #pragma unroll
    for (int r = 0; r < 3; r++) {
        int item = r * 256 + tid;
        int side = (item >= 384) ? 1 : 0;
        int rem = item - side * 384;
        int j = rem / 12, sub = rem - j * 12;
        int m = sub >> 2, e4 = sub & 3;
        const float* W11 = side ? Wv11 : Wk11;

        float4 acc = {0, 0, 0, 0};
        const float* h1p = sm + BH1 + j * 48 + m;
        #pragma unroll
        for (int c = 0; c < 16; c++) {
            float hv = h1p[c * 3];
            float4 w = ((const float4*)(W11 + c * 16))[e4];
            acc.x += hv * w.x; acc.y += hv * w.y; acc.z += hv * w.z; acc.w += hv * w.w;
        }
        float rm = sm[BGEO + j * 4 + m];
        float* out = sm + (side ? BV1 : BK1) + j * 48;
        const float* s01 = sm + BS01 + side * 512 + j * 16;
        const float* s11 = sm + BS11 + side * 512 + j * 16;
        const float* r1 = sm + BR1 + j * 16;
        #pragma unroll
        for (int i = 0; i < 4; i++) {
            int e = e4 * 4 + i;
            float val = (((const float*)&acc)[i] + (s01[e] + s11[e]) * rm) * r1[e];
            out[e * 3 + m] = val;
        }
    }
    __syncthreads();

    // ---- P5: finalize logits with degree-1 term ----
    if (tid < 128) {
        int h = tid & 3, j = tid >> 2;
        float lg = 0.0f;
        #pragma unroll
        for (int t = 0; t < 12; t++)
            lg += sm[BQ1 + h * 12 + t] * sm[BK1 + j * 48 + h * 12 + t];
        sm[BLOG + h * 32 + j] = (sm[BLOG + h * 32 + j] + lg) * SCALEc;
    }
    __syncthreads();

    // ---- P6: softmax over neighbors ----
    if (tid < 32) {
        #pragma unroll
        for (int h = 0; h < 4; h++) {
            float x = sm[BLOG + h * 32 + tid];
            float mx = x;
            #pragma unroll
            for (int o = 16; o > 0; o >>= 1) mx = fmaxf(mx, __shfl_xor_sync(0xffffffffu, mx, o));
            float ev = __expf(x - mx);
            float s = ev;
            #pragma unroll
            for (int o = 16; o > 0; o >>= 1) s += __shfl_xor_sync(0xffffffffu, s, o);
            sm[BLOG + h * 32 + tid] = __fdividef(ev, s);
        }
    }
    __syncthreads();

    // ---- P7: weighted sum over neighbors ----
    if (tid < 112) {
        int h = (tid < 64) ? (tid >> 4) : ((tid - 64) / 12);
        float acc = 0.0f;
        #pragma unroll 8
        for (int j = 0; j < 32; j++) {
            float v = (tid < 64) ? sm[BV0 + j * 64 + tid] : sm[BV1 + j * 48 + (tid - 64)];
            acc += sm[BLOG + h * 32 + j] * v;
        }
        sm[BO + tid] = acc;
    }
    __syncthreads();

    // ---- P8: output projection + residual ----
    if (tid < 64) {
        float a = 0.0f;
        #pragma unroll 8
        for (int d = 0; d < 64; d++) a += sm[BO + d] * Wo0[d * 64 + tid];
        g_f0[bn * 64 + tid] += a;
    } else if (tid < 112) {
        int t = tid - 64, e = t / 3, m = t - e * 3;
        float a = 0.0f;
        #pragma unroll
        for (int c = 0; c < 16; c++) a += sm[BO + 64 + c * 3 + m] * Wo1[c * 16 + e];
        g_f1[bn * 48 + t] += a;
    }
}

// ---------------- node-batched fused FF (+ next-layer prenorm + q) ----------------
__global__ void __launch_bounds__(256) ff_kernel(
    const float* __restrict__ F0w1, const float* __restrict__ F0w2,
    const float* __restrict__ F1w1, const float* __restrict__ F1w2,
    const float* __restrict__ Wq0n, const float* __restrict__ Wq1n)
{
    __shared__ __align__(16) float sf0[NB * 64], sf1[NB * 48];
    __shared__ __align__(16) float sg0[NB * 64], sg1[NB * 48];
    __shared__ __align__(16) float sh[NB * 256];
    __shared__ __align__(16) float su[NB * 192];
    __shared__ __align__(16) float sp[4 * NB * 64];
    int nd0 = blockIdx.x * NB;
    int tid = threadIdx.x, wid = tid >> 5, lane = tid & 31;

    // load f (new values written by attn)
    if (tid < 128) ((float4*)sf0)[tid] = ((const float4*)(g_f0 + nd0 * 64))[tid];
    else if (tid < 224) ((float4*)sf1)[tid - 128] = ((const float4*)(g_f1 + nd0 * 48))[tid - 128];
    __syncthreads();

    // prenorm: warp per node
    {
        int nd = wid;
        float x0 = sf0[nd * 64 + lane], x1 = sf0[nd * 64 + 32 + lane];
        float y0 = sf1[nd * 48 + lane], y1 = (lane < 16) ? sf1[nd * 48 + 32 + lane] : 0.0f;
        float s = x0 + x1, s2 = x0 * x0 + x1 * x1, c2 = y0 * y0 + y1 * y1;
        #pragma unroll
        for (int o = 16; o > 0; o >>= 1) {
            s += __shfl_xor_sync(0xffffffffu, s, o);
            s2 += __shfl_xor_sync(0xffffffffu, s2, o);
            c2 += __shfl_xor_sync(0xffffffffu, c2, o);
        }
        float mu = s * (1.0f / 64.0f);
        float rsig = rsqrtf(s2 * (1.0f / 64.0f) - mu * mu + EPSc);
        float rms = rsqrtf(c2 * (1.0f / 16.0f) + EPSc);
        sg0[nd * 64 + lane] = (x0 - mu) * rsig;
        sg0[nd * 64 + 32 + lane] = (x1 - mu) * rsig;
        sg1[nd * 48 + lane] = y0 * rms;
        if (lane < 16) sg1[nd * 48 + 32 + lane] = y1 * rms;
    }
    __syncthreads();

    // hidden: thread = hidden col, 8 nodes
    {
        float acc[NB] = {0, 0, 0, 0, 0, 0, 0, 0};
        #pragma unroll 4
        for (int d4 = 0; d4 < 16; d4++) {
            float4 g[NB];
            #pragma unroll
            for (int nd = 0; nd < NB; nd++) g[nd] = ((const float4*)(sg0 + nd * 64))[d4];
            #pragma unroll
            for (int dd = 0; dd < 4; dd++) {
                float w = F0w1[(d4 * 4 + dd) * 256 + tid];
                #pragma unroll
                for (int nd = 0; nd < NB; nd++) acc[nd] += ((const float*)&g[nd])[dd] * w;
            }
        }
        #pragma unroll
        for (int nd = 0; nd < NB; nd++) sh[nd * 256 + tid] = gelu_t(acc[nd]);
    }
    // u1 + gate: thread = (nd, elo); handles e = elo and elo+32
    {
        int nd = tid >> 5, elo = tid & 31;
        float a0[3] = {0, 0, 0}, a1[3] = {0, 0, 0};
        #pragma unroll
        for (int c = 0; c < 16; c++) {
            float w0 = F1w1[c * 64 + elo], w1 = F1w1[c * 64 + elo + 32];
            float m0 = sg1[nd * 48 + c * 3 + 0];
            float m1 = sg1[nd * 48 + c * 3 + 1];
            float m2 = sg1[nd * 48 + c * 3 + 2];
            a0[0] += m0 * w0; a0[1] += m1 * w0; a0[2] += m2 * w0;
            a1[0] += m0 * w1; a1[1] += m1 * w1; a1[2] += m2 * w1;
        }
        float g0 = sigmoid_f(sqrtf(a0[0] * a0[0] + a0[1] * a0[1] + a0[2] * a0[2]));
        float g1v = sigmoid_f(sqrtf(a1[0] * a1[0] + a1[1] * a1[1] + a1[2] * a1[2]));
        #pragma unroll
        for (int m = 0; m < 3; m++) {
            su[nd * 192 + elo * 3 + m] = a0[m] * g0;
            su[nd * 192 + (elo + 32) * 3 + m] = a1[m] * g1v;
        }
    }
    __syncthreads();

    // f0 out: partial sums over i-chunks
    {
        int col = tid & 63, chunk = tid >> 6;
        float acc[NB] = {0, 0, 0, 0, 0, 0, 0, 0};
        #pragma unroll 4
        for (int i4 = 0; i4 < 16; i4++) {
            float4 h[NB];
            #pragma unroll
            for (int nd = 0; nd < NB; nd++) h[nd] = ((const float4*)(sh + nd * 256))[chunk * 16 + i4];
            #pragma unroll
            for (int ii = 0; ii < 4; ii++) {
                float w = F0w2[(chunk * 64 + i4 * 4 + ii) * 64 + col];
                #pragma unroll
                for (int nd = 0; nd < NB; nd++) acc[nd] += ((const float*)&h[nd])[ii] * w;
            }
        }
        #pragma unroll
        for (int nd = 0; nd < NB; nd++) sp[(chunk * NB + nd) * 64 + col] = acc[nd];
    }
    __syncthreads();
    // reduce + residual for f0; f1 out
    #pragma unroll
    for (int r = 0; r < 2; r++) {
        int o = r * 256 + tid;
        int nd = o >> 6, col = o & 63;
        float v = sf0[nd * 64 + col]
                + sp[nd * 64 + col] + sp[(NB + nd) * 64 + col]
                + sp[(2 * NB + nd) * 64 + col] + sp[(3 * NB + nd) * 64 + col];
        sf0[nd * 64 + col] = v;
        g_f0[(nd0 + nd) * 64 + col] = v;
    }
    if (tid < 128) {
        int nd = tid >> 4, f = tid & 15;
        float a0 = 0, a1 = 0, a2 = 0;
        #pragma unroll 8
        for (int e = 0; e < 64; e++) {
            float w = F1w2[e * 16 + f];
            a0 += su[nd * 192 + e * 3 + 0] * w;
            a1 += su[nd * 192 + e * 3 + 1] * w;
            a2 += su[nd * 192 + e * 3 + 2] * w;
        }
        float v0 = sf1[nd * 48 + f * 3 + 0] + a0;
        float v1 = sf1[nd * 48 + f * 3 + 1] + a1;
        float v2 = sf1[nd * 48 + f * 3 + 2] + a2;
        sf1[nd * 48 + f * 3 + 0] = v0; g_f1[(nd0 + nd) * 48 + f * 3 + 0] = v0;
        sf1[nd * 48 + f * 3 + 1] = v1; g_f1[(nd0 + nd) * 48 + f * 3 + 1] = v1;
        sf1[nd * 48 + f * 3 + 2] = v2; g_f1[(nd0 + nd) * 48 + f * 3 + 2] = v2;
    }

    if (Wq0n == nullptr) return;
    __syncthreads();

    // ---- next-layer prenorm + q precompute ----
    {
        int nd = wid;
        float x0 = sf0[nd * 64 + lane], x1 = sf0[nd * 64 + 32 + lane];
        float y0 = sf1[nd * 48 + lane], y1 = (lane < 16) ? sf1[nd * 48 + 32 + lane] : 0.0f;
        float s = x0 + x1, s2 = x0 * x0 + x1 * x1, c2 = y0 * y0 + y1 * y1;
        #pragma unroll
        for (int o = 16; o > 0; o >>= 1) {
            s += __shfl_xor_sync(0xffffffffu, s, o);
            s2 += __shfl_xor_sync(0xffffffffu, s2, o);
            c2 += __shfl_xor_sync(0xffffffffu, c2, o);
        }
        float mu = s * (1.0f / 64.0f);
        float rsig = rsqrtf(s2 * (1.0f / 64.0f) - mu * mu + EPSc);
        float rms = rsqrtf(c2 * (1.0f / 16.0f) + EPSc);
        float a0 = (x0 - mu) * rsig, a1 = (x1 - mu) * rsig;
        sg0[nd * 64 + lane] = a0; sg0[nd * 64 + 32 + lane] = a1;
        g_g0[(nd0 + nd) * 64 + lane] = a0; g_g0[(nd0 + nd) * 64 + 32 + lane] = a1;
        float b0 = y0 * rms;
        sg1[nd * 48 + lane] = b0; g_g1[(nd0 + nd) * 48 + lane] = b0;
        if (lane < 16) {
            float b1 = y1 * rms;
            sg1[nd * 48 + 32 + lane] = b1; g_g1[(nd0 + nd) * 48 + 32 + lane] = b1;
        }
    }
    __syncthreads();

    // q0
    {
        int col = tid & 63, chunk = tid >> 6;
        float acc[NB] = {0, 0, 0, 0, 0, 0, 0, 0};
        #pragma unroll
        for (int d4 = 0; d4 < 4; d4++) {
            float4 g[NB];
            #pragma unroll
            for (int nd = 0; nd < NB; nd++) g[nd] = ((const float4*)(sg0 + nd * 64))[chunk * 4 + d4];
            #pragma unroll
            for (int dd = 0; dd < 4; dd++) {
                float w = Wq0n[(chunk * 16 + d4 * 4 + dd) * 64 + col];
                #pragma unroll
                for (int nd = 0; nd < NB; nd++) acc[nd] += ((const float*)&g[nd])[dd] * w;
            }
        }
        #pragma unroll
        for (int nd = 0; nd < NB; nd++) sp[(chunk * NB + nd) * 64 + col] = acc[nd];
    }
    __syncthreads();
    #pragma unroll
    for (int r = 0; r < 2; r++) {
        int o = r * 256 + tid;
        int nd = o >> 6, col = o & 63;
        float v = sp[nd * 64 + col] + sp[(NB + nd) * 64 + col]
                + sp[(2 * NB + nd) * 64 + col] + sp[(3 * NB + nd) * 64 + col];
        g_q0[(nd0 + nd) * 64 + col] = v;
    }
    if (tid < 128) {
        int nd = tid >> 4, e = tid & 15;
        float a0 = 0, a1 = 0, a2 = 0;
        #pragma unroll
        for (int c = 0; c < 16; c++) {
            float w = Wq1n[c * 16 + e];
            a0 += sg1[nd * 48 + c * 3 + 0] * w;
            a1 += sg1[nd * 48 + c * 3 + 1] * w;
            a2 += sg1[nd * 48 + c * 3 + 2] * w;
        }
        g_q1[(nd0 + nd) * 48 + e * 3 + 0] = a0;
        g_q1[(nd0 + nd) * 48 + e * 3 + 1] = a1;
        g_q1[(nd0 + nd) * 48 + e * 3 + 2] = a2;
    }
}

// ---------------- concat to output ----------------
__global__ void concat_kernel(float* __restrict__ out) {
    int i = blockIdx.x * blockDim.x + threadIdx.x;
    if (i >= NN * 112) return;
    int bn = i / 112, c = i - bn * 112;
    out[i] = (c < 64) ? g_f0[bn * 64 + c] : g_f1[bn * 48 + (c - 64)];
}

// ---------------- launch ----------------
extern "C" void kernel_launch(void* const* d_in, const int* in_sizes, int n_in,
                              void* d_out, int out_size) {
    const float* f0 = (const float*)d_in[0];
    const float* f1 = (const float*)d_in[1];
    const float* coords = (const float*)d_in[2];
    const int* nbr = (const int*)d_in[3];
    const float* Wq0 = (const float*)d_in[4];
    const float* Wq1 = (const float*)d_in[5];
    const float* Wk00 = (const float*)d_in[6];
    const float* Wk10 = (const float*)d_in[7];
    const float* Wk01 = (const float*)d_in[8];
    const float* Wk11 = (const float*)d_in[9];
    const float* Wk11r = (const float*)d_in[10];
    const float* Wv00 = (const float*)d_in[11];
    const float* Wv10 = (const float*)d_in[12];
    const float* Wv01 = (const float*)d_in[13];
    const float* Wv11 = (const float*)d_in[14];
    const float* Wv11r = (const float*)d_in[15];
    const float* Rw1 = (const float*)d_in[16];
    const float* Rb1 = (const float*)d_in[17];
    const float* Rw20 = (const float*)d_in[18];
    const float* Rw21 = (const float*)d_in[19];
    const float* Wo0 = (const float*)d_in[20];
    const float* Wo1 = (const float*)d_in[21];
    const float* F0w1 = (const float*)d_in[22];
    const float* F0w2 = (const float*)d_in[23];
    const float* F1w1 = (const float*)d_in[24];
    const float* F1w2 = (const float*)d_in[25];
    float* out = (float*)d_out;

    cudaFuncSetAttribute(attn_kernel, cudaFuncAttributeMaxDynamicSharedMemorySize, SM_BYTES);

    geom_kernel<<<(NN * Kc + 255) / 256, 256>>>(coords, nbr);
    prenorm_q_init_kernel<<<NN / NB, 256>>>(f0, f1, Wq0, Wq1);

    for (int l = 0; l < 2; l++) {
        attn_kernel<<<NN, 256, SM_BYTES>>>(
            nbr,
            Wk00 + l * 64 * 64, Wk10 + l * 16 * 64,
            Wk01 + l * 64 * 16, Wk11 + l * 16 * 16, Wk11r + l * 16 * 16,
            Wv00 + l * 64 * 64, Wv10 + l * 16 * 64,
            Wv01 + l * 64 * 16, Wv11 + l * 16 * 16, Wv11r + l * 16 * 16,
            Rw1 + l * 16, Rb1 + l * 16,
            Rw20 + l * 16 * 64, Rw21 + l * 16 * 16,
            Wo0 + l * 64 * 64, Wo1 + l * 16 * 16);
        const float* nq0 = (l == 0) ? (Wq0 + 64 * 64) : nullptr;
        const float* nq1 = (l == 0) ? (Wq1 + 16 * 16) : nullptr;
        ff_kernel<<<NN / NB, 256>>>(
            F0w1 + l * 64 * 256, F0w2 + l * 256 * 64,
            F1w1 + l * 16 * 64, F1w2 + l * 64 * 16,
            nq0, nq1);
    }
    concat_kernel<<<(NN * 112 + 255) / 256, 256>>>(out);
}

// round 10
// speedup vs baseline: 1.5963x; 1.0387x over previous
#include <cuda_runtime.h>
#include <math.h>
#include <stdint.h>

#define DEV_INLINE __device__ __forceinline__

// ---------------- problem constants ----------------
constexpr int Bc = 2, Nc = 4096, Kc = 32, NB = 8;
constexpr int NN = Bc * Nc;                 // 8192 nodes
constexpr float EPSc = 1e-6f;
constexpr float SCALEc = 0.18898223650461362f;  // 1/sqrt(28)

// ---------------- device scratch ----------------
__device__ float g_f0[NN * 64];
__device__ float g_f1[NN * 48];
__device__ float g_g0[NN * 64];
__device__ float g_g1[NN * 48];
__device__ float g_q0[NN * 64];
__device__ float g_q1[NN * 48];
__device__ float g_rhat[NN * Kc * 3];
__device__ float g_dist[NN * Kc];

// ---------------- packed fp32x2 helpers (SASS FFMA2 path) ----------------
DEV_INLINE uint64_t pack2(float lo, float hi) {
    uint64_t r;
    asm("mov.b64 %0, {%1, %2};" : "=l"(r) : "f"(lo), "f"(hi));
    return r;
}
DEV_INLINE uint64_t dup2(float v) {
    uint64_t r;
    asm("mov.b64 %0, {%1, %1};" : "=l"(r) : "f"(v));
    return r;
}
DEV_INLINE void fma2(uint64_t& acc, uint64_t a, uint64_t b) {
    asm("fma.rn.f32x2 %0, %1, %2, %0;" : "+l"(acc) : "l"(a), "l"(b));
}
DEV_INLINE uint64_t mul2(uint64_t a, uint64_t b) {
    uint64_t r;
    asm("mul.rn.f32x2 %0, %1, %2;" : "=l"(r) : "l"(a), "l"(b));
    return r;
}
DEV_INLINE float2 unpack2(uint64_t v) {
    float lo, hi;
    asm("mov.b64 {%0, %1}, %2;" : "=f"(lo), "=f"(hi) : "l"(v));
    return make_float2(lo, hi);
}

DEV_INLINE float tanh_fast(float z) {
    z = fminf(fmaxf(z, -10.0f), 10.0f);
    float e = __expf(2.0f * z);
    return __fdividef(e - 1.0f, e + 1.0f);
}
DEV_INLINE float gelu_t(float x) {
    float x3 = x * x * x;
    return 0.5f * x * (1.0f + tanh_fast(0.7978845608028654f * (x + 0.044715f * x3)));
}
DEV_INLINE float sigmoid_f(float x) { return __fdividef(1.0f, 1.0f + __expf(-x)); }

// ---------------- geometry ----------------
__global__ void geom_kernel(const float* __restrict__ coords, const int* __restrict__ nbr) {
    int idx = blockIdx.x * blockDim.x + threadIdx.x;
    if (idx >= NN * Kc) return;
    int bn = idx / Kc;
    int b = bn / Nc;
    int gi = b * Nc + nbr[idx];
    float dx = coords[gi * 3 + 0] - coords[bn * 3 + 0];
    float dy = coords[gi * 3 + 1] - coords[bn * 3 + 1];
    float dz = coords[gi * 3 + 2] - coords[bn * 3 + 2];
    float d = sqrtf(dx * dx + dy * dy + dz * dz);
    g_dist[idx] = d;
    float inv = 1.0f / (d + EPSc);
    g_rhat[idx * 3 + 0] = dx * inv;
    g_rhat[idx * 3 + 1] = dy * inv;
    g_rhat[idx * 3 + 2] = dz * inv;
}

// ---------------- init: copy f, prenorm, q0/q1 for layer 0 (8 nodes/block) ----------------
__global__ void __launch_bounds__(256) prenorm_q_init_kernel(
    const float* __restrict__ f0in, const float* __restrict__ f1in,
    const float* __restrict__ Wq0, const float* __restrict__ Wq1)
{
    __shared__ __align__(16) float sf0[NB * 64], sf1[NB * 48];
    __shared__ __align__(16) float sg0[NB * 64], sg1[NB * 48];
    __shared__ __align__(16) float sp[4 * NB * 64];
    int nd0 = blockIdx.x * NB;
    int tid = threadIdx.x, wid = tid >> 5, lane = tid & 31;

    if (tid < 128) {
        float4 v = ((const float4*)(f0in + nd0 * 64))[tid];
        ((float4*)sf0)[tid] = v;
        ((float4*)(g_f0 + nd0 * 64))[tid] = v;
    } else {
        int t = tid - 128;
        if (t < 96) {
            float4 v = ((const float4*)(f1in + nd0 * 48))[t];
            ((float4*)sf1)[t] = v;
            ((float4*)(g_f1 + nd0 * 48))[t] = v;
        }
    }
    __syncthreads();

    {
        int nd = wid;
        float x0 = sf0[nd * 64 + lane], x1 = sf0[nd * 64 + 32 + lane];
        float y0 = sf1[nd * 48 + lane], y1 = (lane < 16) ? sf1[nd * 48 + 32 + lane] : 0.0f;
        float s = x0 + x1, s2 = x0 * x0 + x1 * x1, c2 = y0 * y0 + y1 * y1;
        #pragma unroll
        for (int o = 16; o > 0; o >>= 1) {
            s += __shfl_xor_sync(0xffffffffu, s, o);
            s2 += __shfl_xor_sync(0xffffffffu, s2, o);
            c2 += __shfl_xor_sync(0xffffffffu, c2, o);
        }
        float mu = s * (1.0f / 64.0f);
        float rsig = rsqrtf(s2 * (1.0f / 64.0f) - mu * mu + EPSc);
        float rms = rsqrtf(c2 * (1.0f / 16.0f) + EPSc);
        float a0 = (x0 - mu) * rsig, a1 = (x1 - mu) * rsig;
        sg0[nd * 64 + lane] = a0; sg0[nd * 64 + 32 + lane] = a1;
        g_g0[(nd0 + nd) * 64 + lane] = a0; g_g0[(nd0 + nd) * 64 + 32 + lane] = a1;
        float b0 = y0 * rms;
        sg1[nd * 48 + lane] = b0; g_g1[(nd0 + nd) * 48 + lane] = b0;
        if (lane < 16) {
            float b1 = y1 * rms;
            sg1[nd * 48 + 32 + lane] = b1; g_g1[(nd0 + nd) * 48 + 32 + lane] = b1;
        }
    }
    __syncthreads();

    // q0 = g0 @ Wq0 (chunked over d)
    {
        int col = tid & 63, chunk = tid >> 6;
        float acc[NB] = {0, 0, 0, 0, 0, 0, 0, 0};
        #pragma unroll
        for (int d4 = 0; d4 < 4; d4++) {
            float4 g[NB];
            #pragma unroll
            for (int nd = 0; nd < NB; nd++) g[nd] = ((const float4*)(sg0 + nd * 64))[chunk * 4 + d4];
            #pragma unroll
            for (int dd = 0; dd < 4; dd++) {
                float w = Wq0[(chunk * 16 + d4 * 4 + dd) * 64 + col];
                #pragma unroll
                for (int nd = 0; nd < NB; nd++) acc[nd] += ((const float*)&g[nd])[dd] * w;
            }
        }
        #pragma unroll
        for (int nd = 0; nd < NB; nd++) sp[(chunk * NB + nd) * 64 + col] = acc[nd];
    }
    __syncthreads();
    #pragma unroll
    for (int r = 0; r < 2; r++) {
        int o = r * 256 + tid;
        int nd = o >> 6, col = o & 63;
        float v = sp[nd * 64 + col] + sp[(NB + nd) * 64 + col]
                + sp[(2 * NB + nd) * 64 + col] + sp[(3 * NB + nd) * 64 + col];
        g_q0[(nd0 + nd) * 64 + col] = v;
    }
    if (tid < 128) {
        int nd = tid >> 4, e = tid & 15;
        float a0 = 0, a1 = 0, a2 = 0;
        #pragma unroll
        for (int c = 0; c < 16; c++) {
            float w = Wq1[c * 16 + e];
            a0 += sg1[nd * 48 + c * 3 + 0] * w;
            a1 += sg1[nd * 48 + c * 3 + 1] * w;
            a2 += sg1[nd * 48 + c * 3 + 2] * w;
        }
        g_q1[(nd0 + nd) * 48 + e * 3 + 0] = a0;
        g_q1[(nd0 + nd) * 48 + e * 3 + 1] = a1;
        g_q1[(nd0 + nd) * 48 + e * 3 + 2] = a2;
    }
}

// ---------------- fused attention kernel ----------------
constexpr int BH0 = 0;        // h0[j][d]        32*64
constexpr int BH1 = 2048;     // h1[j][t]        32*48
constexpr int BGEO = 3584;    // [j][rx,ry,rz,d] 32*4
constexpr int BDOT = 3712;    // dot1[j][c]      32*16
constexpr int BRH = 4224;     // rh[j][i]        32*16
constexpr int BR1 = 4736;     // r1[j][e]        32*16
constexpr int BS01 = 5248;    // [side][j][e]    2*32*16
constexpr int BS11 = 6272;    // [side][j][e]    2*32*16
constexpr int BK1 = 7296;     // k1[j][t]        32*48
constexpr int BV1 = 8832;     // v1[j][t]        32*48
constexpr int BV0 = 10368;    // v0[j][d]        32*64
constexpr int BQ0 = 12416;    // 64
constexpr int BQ1 = 12480;    // 48
constexpr int BLOG = 12528;   // 4*32
constexpr int BO = 12656;     // 112
constexpr int SM_FLOATS = 12768;
constexpr int SM_BYTES = SM_FLOATS * 4;  // 51072

__global__ void __launch_bounds__(256, 3) attn_kernel(
    const int* __restrict__ nbr,
    const float* __restrict__ Wk00, const float* __restrict__ Wk10,
    const float* __restrict__ Wk01, const float* __restrict__ Wk11, const float* __restrict__ Wk11r,
    const float* __restrict__ Wv00, const float* __restrict__ Wv10,
    const float* __restrict__ Wv01, const float* __restrict__ Wv11, const float* __restrict__ Wv11r,
    const float* __restrict__ Rw1, const float* __restrict__ Rb1,
    const float* __restrict__ Rw20, const float* __restrict__ Rw21,
    const float* __restrict__ Wo0, const float* __restrict__ Wo1)
{
    extern __shared__ float sm[];
    int bn = blockIdx.x;
    int b = bn >> 12;  // Nc = 4096
    int tid = threadIdx.x;
    int wid = tid >> 5;
    int lane = tid & 31;

    // ---- P0: load precomputed q0/q1 + stage 32 neighbors ----
    if (tid < 16) {
        ((float4*)(sm + BQ0))[tid] = ((const float4*)(g_q0 + bn * 64))[tid];
    } else if (tid < 28) {
        ((float4*)(sm + BQ1))[tid - 16] = ((const float4*)(g_q1 + bn * 48))[tid - 16];
    }
    {
        int jb = wid * 4;
        int js[4];
        #pragma unroll
        for (int q = 0; q < 4; q++) js[q] = nbr[bn * Kc + jb + q];
        #pragma unroll
        for (int u = lane; u < 64; u += 32) {
            int q = u >> 4, v = u & 15;
            int gi = b * Nc + js[q];
            ((float4*)(sm + BH0))[(jb + q) * 16 + v] = ((const float4*)g_g0)[gi * 16 + v];
        }
        #pragma unroll
        for (int u = lane; u < 48; u += 32) {
            int q = u / 12, v = u - q * 12;
            int gi = b * Nc + js[q];
            ((float4*)(sm + BH1))[(jb + q) * 12 + v] = ((const float4*)g_g1)[gi * 12 + v];
        }
        if (lane < 16) {
            int q = lane >> 2, comp = lane & 3;
            int e = bn * Kc + jb + q;
            sm[BGEO + (jb + q) * 4 + comp] = (comp < 3) ? g_rhat[e * 3 + comp] : g_dist[e];
        }
    }
    __syncthreads();

    // ---- P1: dot1[j][c], rh[j][c] ----
    #pragma unroll
    for (int u = tid; u < 512; u += 256) {
        int j = u >> 4, c = u & 15;
        const float* h1p = sm + BH1 + j * 48 + c * 3;
        const float* gp = sm + BGEO + j * 4;
        sm[BDOT + u] = h1p[0] * gp[0] + h1p[1] * gp[1] + h1p[2] * gp[2];
        sm[BRH + u] = gelu_t(gp[3] * Rw1[c] + Rb1[c]);
    }
    __syncthreads();

    // ---- P2: s01 = h0@W01, s11 = dot1@W11r, r1 = rh@Rw21 (packed f32x2) ----
    {
        int side = tid >> 7;       // 0=K, 1=V
        int j = (tid >> 2) & 31;
        int e4 = tid & 3;
        const float* W01 = side ? Wv01 : Wk01;
        const float* W11r = side ? Wv11r : Wk11r;

        uint64_t alo = 0, ahi = 0;
        const float4* h0v = (const float4*)(sm + BH0 + j * 64);
        #pragma unroll 4
        for (int d4 = 0; d4 < 16; d4++) {
            float4 h = h0v[d4];
            #pragma unroll
            for (int dd = 0; dd < 4; dd++) {
                uint64_t h2 = dup2(((const float*)&h)[dd]);
                ulonglong2 w = *((const ulonglong2*)(W01 + (d4 * 4 + dd) * 16) + e4);
                fma2(alo, w.x, h2); fma2(ahi, w.y, h2);
            }
        }
        *((ulonglong2*)(sm + BS01) + side * 128 + j * 4 + e4) = make_ulonglong2(alo, ahi);

        uint64_t blo = 0, bhi = 0;
        const float* dt = sm + BDOT + j * 16;
        #pragma unroll
        for (int c = 0; c < 16; c++) {
            uint64_t h2 = dup2(dt[c]);
            ulonglong2 w = *((const ulonglong2*)(W11r + c * 16) + e4);
            fma2(blo, w.x, h2); fma2(bhi, w.y, h2);
        }
        *((ulonglong2*)(sm + BS11) + side * 128 + j * 4 + e4) = make_ulonglong2(blo, bhi);

        if (side == 0) {
            uint64_t rlo = 0, rhi = 0;
            const float* rh = sm + BRH + j * 16;
            #pragma unroll
            for (int i = 0; i < 16; i++) {
                uint64_t h2 = dup2(rh[i]);
                ulonglong2 w = *((const ulonglong2*)(Rw21 + i * 16) + e4);
                fma2(rlo, w.x, h2); fma2(rhi, w.y, h2);
            }
            *((ulonglong2*)(sm + BR1) + j * 4 + e4) = make_ulonglong2(rlo, rhi);
        }
    }
    __syncthreads();

    // ---- P3: main k0/v0 GEMM — packed channel pair (c0, c0+1) per lane ----
    {
        int side = wid & 1;
        int jb = (wid >> 1) * 8;
        const float* W00 = side ? Wv00 : Wk00;
        const float* W10 = side ? Wv10 : Wk10;
        int c0 = lane * 2;

        uint64_t acc[8] = {0, 0, 0, 0, 0, 0, 0, 0};
        #pragma unroll 2
        for (int d4 = 0; d4 < 16; d4++) {
            float4 h[8];
            #pragma unroll
            for (int q = 0; q < 8; q++) h[q] = ((const float4*)(sm + BH0 + (jb + q) * 64))[d4];
            #pragma unroll
            for (int dd = 0; dd < 4; dd++) {
                uint64_t w2 = *(const uint64_t*)(W00 + (d4 * 4 + dd) * 64 + c0);
                #pragma unroll
                for (int q = 0; q < 8; q++)
                    fma2(acc[q], w2, dup2(((const float*)&h[q])[dd]));
            }
        }
        #pragma unroll
        for (int e4 = 0; e4 < 4; e4++) {
            float4 h[8];
            #pragma unroll
            for (int q = 0; q < 8; q++) h[q] = ((const float4*)(sm + BDOT + (jb + q) * 16))[e4];
            #pragma unroll
            for (int ee = 0; ee < 4; ee++) {
                uint64_t w2 = *(const uint64_t*)(W10 + (e4 * 4 + ee) * 64 + c0);
                #pragma unroll
                for (int q = 0; q < 8; q++)
                    fma2(acc[q], w2, dup2(((const float*)&h[q])[ee]));
            }
        }
        uint64_t r0acc[8] = {0, 0, 0, 0, 0, 0, 0, 0};
        #pragma unroll
        for (int e4 = 0; e4 < 4; e4++) {
            float4 h[8];
            #pragma unroll
            for (int q = 0; q < 8; q++) h[q] = ((const float4*)(sm + BRH + (jb + q) * 16))[e4];
            #pragma unroll
            for (int ee = 0; ee < 4; ee++) {
                uint64_t w2 = *(const uint64_t*)(Rw20 + (e4 * 4 + ee) * 64 + c0);
                #pragma unroll
                for (int q = 0; q < 8; q++)
                    fma2(r0acc[q], w2, dup2(((const float*)&h[q])[ee]));
            }
        }

        if (side) {
            #pragma unroll
            for (int q = 0; q < 8; q++)
                *(uint64_t*)(sm + BV0 + (jb + q) * 64 + c0) = mul2(acc[q], r0acc[q]);
        } else {
            float2 q0p = *(const float2*)(sm + BQ0 + c0);
            float la[8];
            #pragma unroll
            for (int q = 0; q < 8; q++) {
                float2 k = unpack2(mul2(acc[q], r0acc[q]));
                la[q] = q0p.x * k.x + q0p.y * k.y;
            }
            #pragma unroll
            for (int o = 4; o > 0; o >>= 1) {
                #pragma unroll
                for (int q = 0; q < 8; q++)
                    la[q] += __shfl_xor_sync(0xffffffffu, la[q], o);
            }
            if ((lane & 7) == 0) {
                int h = lane >> 3;
                #pragma unroll
                for (int q = 0; q < 8; q++) sm[BLOG + h * 32 + jb + q] = la[q];
            }
        }
    }

    // ---- P4: k1/v1 assembly (packed) ----
    #pragma unroll
    for (int r = 0; r < 3; r++) {
        int item = r * 256 + tid;
        int side = (item >= 384) ? 1 : 0;
        int rem = item - side * 384;
        int j = rem / 12, sub = rem - j * 12;
        int m = sub >> 2, e4 = sub & 3;
        const float* W11 = side ? Wv11 : Wk11;

        uint64_t alo = 0, ahi = 0;
        const float* h1p = sm + BH1 + j * 48 + m;
        #pragma unroll
        for (int c = 0; c < 16; c++) {
            uint64_t h2 = dup2(h1p[c * 3]);
            ulonglong2 w = *((const ulonglong2*)(W11 + c * 16) + e4);
            fma2(alo, w.x, h2); fma2(ahi, w.y, h2);
        }
        float2 a01 = unpack2(alo), a23 = unpack2(ahi);
        float av[4] = {a01.x, a01.y, a23.x, a23.y};
        float rm = sm[BGEO + j * 4 + m];
        float* out = sm + (side ? BV1 : BK1) + j * 48;
        const float* s01 = sm + BS01 + side * 512 + j * 16;
        const float* s11 = sm + BS11 + side * 512 + j * 16;
        const float* r1 = sm + BR1 + j * 16;
        #pragma unroll
        for (int i = 0; i < 4; i++) {
            int e = e4 * 4 + i;
            float val = (av[i] + (s01[e] + s11[e]) * rm) * r1[e];
            out[e * 3 + m] = val;
        }
    }
    __syncthreads();

    // ---- P5: finalize logits with degree-1 term ----
    if (tid < 128) {
        int h = tid & 3, j = tid >> 2;
        float lg = 0.0f;
        #pragma unroll
        for (int t = 0; t < 12; t++)
            lg += sm[BQ1 + h * 12 + t] * sm[BK1 + j * 48 + h * 12 + t];
        sm[BLOG + h * 32 + j] = (sm[BLOG + h * 32 + j] + lg) * SCALEc;
    }
    __syncthreads();

    // ---- P6: softmax over neighbors ----
    if (tid < 32) {
        #pragma unroll
        for (int h = 0; h < 4; h++) {
            float x = sm[BLOG + h * 32 + tid];
            float mx = x;
            #pragma unroll
            for (int o = 16; o > 0; o >>= 1) mx = fmaxf(mx, __shfl_xor_sync(0xffffffffu, mx, o));
            float ev = __expf(x - mx);
            float s = ev;
            #pragma unroll
            for (int o = 16; o > 0; o >>= 1) s += __shfl_xor_sync(0xffffffffu, s, o);
            sm[BLOG + h * 32 + tid] = __fdividef(ev, s);
        }
    }
    __syncthreads();

    // ---- P7: weighted sum over neighbors ----
    if (tid < 112) {
        int h = (tid < 64) ? (tid >> 4) : ((tid - 64) / 12);
        float acc = 0.0f;
        #pragma unroll 8
        for (int j = 0; j < 32; j++) {
            float v = (tid < 64) ? sm[BV0 + j * 64 + tid] : sm[BV1 + j * 48 + (tid - 64)];
            acc += sm[BLOG + h * 32 + j] * v;
        }
        sm[BO + tid] = acc;
    }
    __syncthreads();

    // ---- P8: output projection + residual ----
    if (tid < 64) {
        float a = 0.0f;
        #pragma unroll 8
        for (int d = 0; d < 64; d++) a += sm[BO + d] * Wo0[d * 64 + tid];
        g_f0[bn * 64 + tid] += a;
    } else if (tid < 112) {
        int t = tid - 64, e = t / 3, m = t - e * 3;
        float a = 0.0f;
        #pragma unroll
        for (int c = 0; c < 16; c++) a += sm[BO + 64 + c * 3 + m] * Wo1[c * 16 + e];
        g_f1[bn * 48 + t] += a;
    }
}

// ---------------- node-batched fused FF (+ next-layer prenorm + q) ----------------
__global__ void __launch_bounds__(256) ff_kernel(
    const float* __restrict__ F0w1, const float* __restrict__ F0w2,
    const float* __restrict__ F1w1, const float* __restrict__ F1w2,
    const float* __restrict__ Wq0n, const float* __restrict__ Wq1n)
{
    __shared__ __align__(16) float sf0[NB * 64], sf1[NB * 48];
    __shared__ __align__(16) float sg0[NB * 64], sg1[NB * 48];
    __shared__ __align__(16) float sh[NB * 256];
    __shared__ __align__(16) float su[NB * 192];
    __shared__ __align__(16) float sp[4 * NB * 64];
    int nd0 = blockIdx.x * NB;
    int tid = threadIdx.x, wid = tid >> 5, lane = tid & 31;

    if (tid < 128) ((float4*)sf0)[tid] = ((const float4*)(g_f0 + nd0 * 64))[tid];
    else if (tid < 224) ((float4*)sf1)[tid - 128] = ((const float4*)(g_f1 + nd0 * 48))[tid - 128];
    __syncthreads();

    {
        int nd = wid;
        float x0 = sf0[nd * 64 + lane], x1 = sf0[nd * 64 + 32 + lane];
        float y0 = sf1[nd * 48 + lane], y1 = (lane < 16) ? sf1[nd * 48 + 32 + lane] : 0.0f;
        float s = x0 + x1, s2 = x0 * x0 + x1 * x1, c2 = y0 * y0 + y1 * y1;
        #pragma unroll
        for (int o = 16; o > 0; o >>= 1) {
            s += __shfl_xor_sync(0xffffffffu, s, o);
            s2 += __shfl_xor_sync(0xffffffffu, s2, o);
            c2 += __shfl_xor_sync(0xffffffffu, c2, o);
        }
        float mu = s * (1.0f / 64.0f);
        float rsig = rsqrtf(s2 * (1.0f / 64.0f) - mu * mu + EPSc);
        float rms = rsqrtf(c2 * (1.0f / 16.0f) + EPSc);
        sg0[nd * 64 + lane] = (x0 - mu) * rsig;
        sg0[nd * 64 + 32 + lane] = (x1 - mu) * rsig;
        sg1[nd * 48 + lane] = y0 * rms;
        if (lane < 16) sg1[nd * 48 + 32 + lane] = y1 * rms;
    }
    __syncthreads();

    // hidden: thread = hidden col, packed node pairs
    {
        uint64_t acc[4] = {0, 0, 0, 0};
        #pragma unroll 4
        for (int d4 = 0; d4 < 16; d4++) {
            float4 g[NB];
            #pragma unroll
            for (int nd = 0; nd < NB; nd++) g[nd] = ((const float4*)(sg0 + nd * 64))[d4];
            #pragma unroll
            for (int dd = 0; dd < 4; dd++) {
                uint64_t w2 = dup2(F0w1[(d4 * 4 + dd) * 256 + tid]);
                #pragma unroll
                for (int p = 0; p < 4; p++)
                    fma2(acc[p], w2, pack2(((const float*)&g[2 * p])[dd], ((const float*)&g[2 * p + 1])[dd]));
            }
        }
        #pragma unroll
        for (int p = 0; p < 4; p++) {
            float2 v = unpack2(acc[p]);
            sh[(2 * p) * 256 + tid] = gelu_t(v.x);
            sh[(2 * p + 1) * 256 + tid] = gelu_t(v.y);
        }
    }
    // u1 + gate
    {
        int nd = tid >> 5, elo = tid & 31;
        float a0[3] = {0, 0, 0}, a1[3] = {0, 0, 0};
        #pragma unroll
        for (int c = 0; c < 16; c++) {
            float w0 = F1w1[c * 64 + elo], w1 = F1w1[c * 64 + elo + 32];
            float m0 = sg1[nd * 48 + c * 3 + 0];
            float m1 = sg1[nd * 48 + c * 3 + 1];
            float m2 = sg1[nd * 48 + c * 3 + 2];
            a0[0] += m0 * w0; a0[1] += m1 * w0; a0[2] += m2 * w0;
            a1[0] += m0 * w1; a1[1] += m1 * w1; a1[2] += m2 * w1;
        }
        float g0 = sigmoid_f(sqrtf(a0[0] * a0[0] + a0[1] * a0[1] + a0[2] * a0[2]));
        float g1v = sigmoid_f(sqrtf(a1[0] * a1[0] + a1[1] * a1[1] + a1[2] * a1[2]));
        #pragma unroll
        for (int m = 0; m < 3; m++) {
            su[nd * 192 + elo * 3 + m] = a0[m] * g0;
            su[nd * 192 + (elo + 32) * 3 + m] = a1[m] * g1v;
        }
    }
    __syncthreads();

    // f0 out: packed node pairs, partial sums over i-chunks
    {
        int col = tid & 63, chunk = tid >> 6;
        uint64_t acc[4] = {0, 0, 0, 0};
        #pragma unroll 4
        for (int i4 = 0; i4 < 16; i4++) {
            float4 h[NB];
            #pragma unroll
            for (int nd = 0; nd < NB; nd++) h[nd] = ((const float4*)(sh + nd * 256))[chunk * 16 + i4];
            #pragma unroll
            for (int ii = 0; ii < 4; ii++) {
                uint64_t w2 = dup2(F0w2[(chunk * 64 + i4 * 4 + ii) * 64 + col]);
                #pragma unroll
                for (int p = 0; p < 4; p++)
                    fma2(acc[p], w2, pack2(((const float*)&h[2 * p])[ii], ((const float*)&h[2 * p + 1])[ii]));
            }
        }
        #pragma unroll
        for (int p = 0; p < 4; p++) {
            float2 v = unpack2(acc[p]);
            sp[(chunk * NB + 2 * p) * 64 + col] = v.x;
            sp[(chunk * NB + 2 * p + 1) * 64 + col] = v.y;
        }
    }
    __syncthreads();
    #pragma unroll
    for (int r = 0; r < 2; r++) {
        int o = r * 256 + tid;
        int nd = o >> 6, col = o & 63;
        float v = sf0[nd * 64 + col]
                + sp[nd * 64 + col] + sp[(NB + nd) * 64 + col]
                + sp[(2 * NB + nd) * 64 + col] + sp[(3 * NB + nd) * 64 + col];
        sf0[nd * 64 + col] = v;
        g_f0[(nd0 + nd) * 64 + col] = v;
    }
    if (tid < 128) {
        int nd = tid >> 4, f = tid & 15;
        float a0 = 0, a1 = 0, a2 = 0;
        #pragma unroll 8
        for (int e = 0; e < 64; e++) {
            float w = F1w2[e * 16 + f];
            a0 += su[nd * 192 + e * 3 + 0] * w;
            a1 += su[nd * 192 + e * 3 + 1] * w;
            a2 += su[nd * 192 + e * 3 + 2] * w;
        }
        float v0 = sf1[nd * 48 + f * 3 + 0] + a0;
        float v1 = sf1[nd * 48 + f * 3 + 1] + a1;
        float v2 = sf1[nd * 48 + f * 3 + 2] + a2;
        sf1[nd * 48 + f * 3 + 0] = v0; g_f1[(nd0 + nd) * 48 + f * 3 + 0] = v0;
        sf1[nd * 48 + f * 3 + 1] = v1; g_f1[(nd0 + nd) * 48 + f * 3 + 1] = v1;
        sf1[nd * 48 + f * 3 + 2] = v2; g_f1[(nd0 + nd) * 48 + f * 3 + 2] = v2;
    }

    if (Wq0n == nullptr) return;
    __syncthreads();

    // ---- next-layer prenorm + q precompute ----
    {
        int nd = wid;
        float x0 = sf0[nd * 64 + lane], x1 = sf0[nd * 64 + 32 + lane];
        float y0 = sf1[nd * 48 + lane], y1 = (lane < 16) ? sf1[nd * 48 + 32 + lane] : 0.0f;
        float s = x0 + x1, s2 = x0 * x0 + x1 * x1, c2 = y0 * y0 + y1 * y1;
        #pragma unroll
        for (int o = 16; o > 0; o >>= 1) {
            s += __shfl_xor_sync(0xffffffffu, s, o);
            s2 += __shfl_xor_sync(0xffffffffu, s2, o);
            c2 += __shfl_xor_sync(0xffffffffu, c2, o);
        }
        float mu = s * (1.0f / 64.0f);
        float rsig = rsqrtf(s2 * (1.0f / 64.0f) - mu * mu + EPSc);
        float rms = rsqrtf(c2 * (1.0f / 16.0f) + EPSc);
        float a0 = (x0 - mu) * rsig, a1 = (x1 - mu) * rsig;
        sg0[nd * 64 + lane] = a0; sg0[nd * 64 + 32 + lane] = a1;
        g_g0[(nd0 + nd) * 64 + lane] = a0; g_g0[(nd0 + nd) * 64 + 32 + lane] = a1;
        float b0 = y0 * rms;
        sg1[nd * 48 + lane] = b0; g_g1[(nd0 + nd) * 48 + lane] = b0;
        if (lane < 16) {
            float b1 = y1 * rms;
            sg1[nd * 48 + 32 + lane] = b1; g_g1[(nd0 + nd) * 48 + 32 + lane] = b1;
        }
    }
    __syncthreads();

    {
        int col = tid & 63, chunk = tid >> 6;
        float acc[NB] = {0, 0, 0, 0, 0, 0, 0, 0};
        #pragma unroll
        for (int d4 = 0; d4 < 4; d4++) {
            float4 g[NB];
            #pragma unroll
            for (int nd = 0; nd < NB; nd++) g[nd] = ((const float4*)(sg0 + nd * 64))[chunk * 4 + d4];
            #pragma unroll
            for (int dd = 0; dd < 4; dd++) {
                float w = Wq0n[(chunk * 16 + d4 * 4 + dd) * 64 + col];
                #pragma unroll
                for (int nd = 0; nd < NB; nd++) acc[nd] += ((const float*)&g[nd])[dd] * w;
            }
        }
        #pragma unroll
        for (int nd = 0; nd < NB; nd++) sp[(chunk * NB + nd) * 64 + col] = acc[nd];
    }
    __syncthreads();
    #pragma unroll
    for (int r = 0; r < 2; r++) {
        int o = r * 256 + tid;
        int nd = o >> 6, col = o & 63;
        float v = sp[nd * 64 + col] + sp[(NB + nd) * 64 + col]
                + sp[(2 * NB + nd) * 64 + col] + sp[(3 * NB + nd) * 64 + col];
        g_q0[(nd0 + nd) * 64 + col] = v;
    }
    if (tid < 128) {
        int nd = tid >> 4, e = tid & 15;
        float a0 = 0, a1 = 0, a2 = 0;
        #pragma unroll
        for (int c = 0; c < 16; c++) {
            float w = Wq1n[c * 16 + e];
            a0 += sg1[nd * 48 + c * 3 + 0] * w;
            a1 += sg1[nd * 48 + c * 3 + 1] * w;
            a2 += sg1[nd * 48 + c * 3 + 2] * w;
        }
        g_q1[(nd0 + nd) * 48 + e * 3 + 0] = a0;
        g_q1[(nd0 + nd) * 48 + e * 3 + 1] = a1;
        g_q1[(nd0 + nd) * 48 + e * 3 + 2] = a2;
    }
}

// ---------------- concat to output ----------------
__global__ void concat_kernel(float* __restrict__ out) {
    int i = blockIdx.x * blockDim.x + threadIdx.x;
    if (i >= NN * 112) return;
    int bn = i / 112, c = i - bn * 112;
    out[i] = (c < 64) ? g_f0[bn * 64 + c] : g_f1[bn * 48 + (c - 64)];
}

// ---------------- launch ----------------
extern "C" void kernel_launch(void* const* d_in, const int* in_sizes, int n_in,
                              void* d_out, int out_size) {
    const float* f0 = (const float*)d_in[0];
    const float* f1 = (const float*)d_in[1];
    const float* coords = (const float*)d_in[2];
    const int* nbr = (const int*)d_in[3];
    const float* Wq0 = (const float*)d_in[4];
    const float* Wq1 = (const float*)d_in[5];
    const float* Wk00 = (const float*)d_in[6];
    const float* Wk10 = (const float*)d_in[7];
    const float* Wk01 = (const float*)d_in[8];
    const float* Wk11 = (const float*)d_in[9];
    const float* Wk11r = (const float*)d_in[10];
    const float* Wv00 = (const float*)d_in[11];
    const float* Wv10 = (const float*)d_in[12];
    const float* Wv01 = (const float*)d_in[13];
    const float* Wv11 = (const float*)d_in[14];
    const float* Wv11r = (const float*)d_in[15];
    const float* Rw1 = (const float*)d_in[16];
    const float* Rb1 = (const float*)d_in[17];
    const float* Rw20 = (const float*)d_in[18];
    const float* Rw21 = (const float*)d_in[19];
    const float* Wo0 = (const float*)d_in[20];
    const float* Wo1 = (const float*)d_in[21];
    const float* F0w1 = (const float*)d_in[22];
    const float* F0w2 = (const float*)d_in[23];
    const float* F1w1 = (const float*)d_in[24];
    const float* F1w2 = (const float*)d_in[25];
    float* out = (float*)d_out;

    cudaFuncSetAttribute(attn_kernel, cudaFuncAttributeMaxDynamicSharedMemorySize, SM_BYTES);

    geom_kernel<<<(NN * Kc + 255) / 256, 256>>>(coords, nbr);
    prenorm_q_init_kernel<<<NN / NB, 256>>>(f0, f1, Wq0, Wq1);

    for (int l = 0; l < 2; l++) {
        attn_kernel<<<NN, 256, SM_BYTES>>>(
            nbr,
            Wk00 + l * 64 * 64, Wk10 + l * 16 * 64,
            Wk01 + l * 64 * 16, Wk11 + l * 16 * 16, Wk11r + l * 16 * 16,
            Wv00 + l * 64 * 64, Wv10 + l * 16 * 64,
            Wv01 + l * 64 * 16, Wv11 + l * 16 * 16, Wv11r + l * 16 * 16,
            Rw1 + l * 16, Rb1 + l * 16,
            Rw20 + l * 16 * 64, Rw21 + l * 16 * 16,
            Wo0 + l * 64 * 64, Wo1 + l * 16 * 16);
        const float* nq0 = (l == 0) ? (Wq0 + 64 * 64) : nullptr;
        const float* nq1 = (l == 0) ? (Wq1 + 16 * 16) : nullptr;
        ff_kernel<<<NN / NB, 256>>>(
            F0w1 + l * 64 * 256, F0w2 + l * 256 * 64,
            F1w1 + l * 16 * 64, F1w2 + l * 64 * 16,
            nq0, nq1);
    }
    concat_kernel<<<(NN * 112 + 255) / 256, 256>>>(out);
}

// round 11
// speedup vs baseline: 2.9125x; 1.8245x over previous
#include <cuda_runtime.h>
#include <math.h>
#include <stdint.h>

#define DEV_INLINE __device__ __forceinline__

// ---------------- problem constants ----------------
constexpr int Bc = 2, Nc = 4096, Kc = 32, NB = 8;
constexpr int NN = Bc * Nc;                 // 8192 nodes
constexpr float EPSc = 1e-6f;
constexpr float SCALEc = 0.18898223650461362f;  // 1/sqrt(28)

// ---------------- device scratch ----------------
__device__ float g_f0[NN * 64];
__device__ float g_f1[NN * 48];
__device__ float g_g0[NN * 64];
__device__ float g_g1[NN * 48];
__device__ float g_q0[NN * 64];
__device__ float g_q1[NN * 48];
__device__ float g_rhat[NN * Kc * 3];
__device__ float g_dist[NN * Kc];
// per-node precomputed neighbor transforms (side 0 = K, side 1 = V)
__device__ float g_A0[NN * 128];    // [node][side][64]   g0 @ W00
__device__ float g_M10[NN * 384];   // [node][side][m][64] einsum(g1, W10)
__device__ float g_S01[NN * 32];    // [node][side][16]   g0 @ W01
__device__ float g_T1[NN * 96];     // [node][side][e*3+m] einsum(g1, W11)
__device__ float g_Mr[NN * 96];     // [node][side][e*3+m] einsum(g1, W11r) (m is the rhat-contraction idx)

// ---------------- packed fp32x2 helpers ----------------
DEV_INLINE uint64_t pack2(float lo, float hi) {
    uint64_t r; asm("mov.b64 %0, {%1, %2};" : "=l"(r) : "f"(lo), "f"(hi)); return r;
}
DEV_INLINE uint64_t dup2(float v) {
    uint64_t r; asm("mov.b64 %0, {%1, %1};" : "=l"(r) : "f"(v)); return r;
}
DEV_INLINE void fma2(uint64_t& acc, uint64_t a, uint64_t b) {
    asm("fma.rn.f32x2 %0, %1, %2, %0;" : "+l"(acc) : "l"(a), "l"(b));
}
DEV_INLINE uint64_t mul2(uint64_t a, uint64_t b) {
    uint64_t r; asm("mul.rn.f32x2 %0, %1, %2;" : "=l"(r) : "l"(a), "l"(b)); return r;
}
DEV_INLINE float2 unpack2(uint64_t v) {
    float lo, hi; asm("mov.b64 {%0, %1}, %2;" : "=f"(lo), "=f"(hi) : "l"(v));
    return make_float2(lo, hi);
}

DEV_INLINE float tanh_fast(float z) {
    z = fminf(fmaxf(z, -10.0f), 10.0f);
    float e = __expf(2.0f * z);
    return __fdividef(e - 1.0f, e + 1.0f);
}
DEV_INLINE float gelu_t(float x) {
    float x3 = x * x * x;
    return 0.5f * x * (1.0f + tanh_fast(0.7978845608028654f * (x + 0.044715f * x3)));
}
DEV_INLINE float sigmoid_f(float x) { return __fdividef(1.0f, 1.0f + __expf(-x)); }

// ---------------- geometry ----------------
__global__ void geom_kernel(const float* __restrict__ coords, const int* __restrict__ nbr) {
    int idx = blockIdx.x * blockDim.x + threadIdx.x;
    if (idx >= NN * Kc) return;
    int bn = idx / Kc;
    int b = bn / Nc;
    int gi = b * Nc + nbr[idx];
    float dx = coords[gi * 3 + 0] - coords[bn * 3 + 0];
    float dy = coords[gi * 3 + 1] - coords[bn * 3 + 1];
    float dz = coords[gi * 3 + 2] - coords[bn * 3 + 2];
    float d = sqrtf(dx * dx + dy * dy + dz * dz);
    g_dist[idx] = d;
    float inv = 1.0f / (d + EPSc);
    g_rhat[idx * 3 + 0] = dx * inv;
    g_rhat[idx * 3 + 1] = dy * inv;
    g_rhat[idx * 3 + 2] = dz * inv;
}

// ---------------- init: copy f, prenorm, q0/q1 for layer 0 ----------------
__global__ void __launch_bounds__(256) prenorm_q_init_kernel(
    const float* __restrict__ f0in, const float* __restrict__ f1in,
    const float* __restrict__ Wq0, const float* __restrict__ Wq1)
{
    __shared__ __align__(16) float sf0[NB * 64], sf1[NB * 48];
    __shared__ __align__(16) float sg0[NB * 64], sg1[NB * 48];
    __shared__ __align__(16) float sp[4 * NB * 64];
    int nd0 = blockIdx.x * NB;
    int tid = threadIdx.x, wid = tid >> 5, lane = tid & 31;

    if (tid < 128) {
        float4 v = ((const float4*)(f0in + nd0 * 64))[tid];
        ((float4*)sf0)[tid] = v;
        ((float4*)(g_f0 + nd0 * 64))[tid] = v;
    } else {
        int t = tid - 128;
        if (t < 96) {
            float4 v = ((const float4*)(f1in + nd0 * 48))[t];
            ((float4*)sf1)[t] = v;
            ((float4*)(g_f1 + nd0 * 48))[t] = v;
        }
    }
    __syncthreads();

    {
        int nd = wid;
        float x0 = sf0[nd * 64 + lane], x1 = sf0[nd * 64 + 32 + lane];
        float y0 = sf1[nd * 48 + lane], y1 = (lane < 16) ? sf1[nd * 48 + 32 + lane] : 0.0f;
        float s = x0 + x1, s2 = x0 * x0 + x1 * x1, c2 = y0 * y0 + y1 * y1;
        #pragma unroll
        for (int o = 16; o > 0; o >>= 1) {
            s += __shfl_xor_sync(0xffffffffu, s, o);
            s2 += __shfl_xor_sync(0xffffffffu, s2, o);
            c2 += __shfl_xor_sync(0xffffffffu, c2, o);
        }
        float mu = s * (1.0f / 64.0f);
        float rsig = rsqrtf(s2 * (1.0f / 64.0f) - mu * mu + EPSc);
        float rms = rsqrtf(c2 * (1.0f / 16.0f) + EPSc);
        float a0 = (x0 - mu) * rsig, a1 = (x1 - mu) * rsig;
        sg0[nd * 64 + lane] = a0; sg0[nd * 64 + 32 + lane] = a1;
        g_g0[(nd0 + nd) * 64 + lane] = a0; g_g0[(nd0 + nd) * 64 + 32 + lane] = a1;
        float b0 = y0 * rms;
        sg1[nd * 48 + lane] = b0; g_g1[(nd0 + nd) * 48 + lane] = b0;
        if (lane < 16) {
            float b1 = y1 * rms;
            sg1[nd * 48 + 32 + lane] = b1; g_g1[(nd0 + nd) * 48 + 32 + lane] = b1;
        }
    }
    __syncthreads();

    {
        int col = tid & 63, chunk = tid >> 6;
        float acc[NB] = {0, 0, 0, 0, 0, 0, 0, 0};
        #pragma unroll
        for (int d4 = 0; d4 < 4; d4++) {
            float4 g[NB];
            #pragma unroll
            for (int nd = 0; nd < NB; nd++) g[nd] = ((const float4*)(sg0 + nd * 64))[chunk * 4 + d4];
            #pragma unroll
            for (int dd = 0; dd < 4; dd++) {
                float w = Wq0[(chunk * 16 + d4 * 4 + dd) * 64 + col];
                #pragma unroll
                for (int nd = 0; nd < NB; nd++) acc[nd] += ((const float*)&g[nd])[dd] * w;
            }
        }
        #pragma unroll
        for (int nd = 0; nd < NB; nd++) sp[(chunk * NB + nd) * 64 + col] = acc[nd];
    }
    __syncthreads();
    #pragma unroll
    for (int r = 0; r < 2; r++) {
        int o = r * 256 + tid;
        int nd = o >> 6, col = o & 63;
        float v = sp[nd * 64 + col] + sp[(NB + nd) * 64 + col]
                + sp[(2 * NB + nd) * 64 + col] + sp[(3 * NB + nd) * 64 + col];
        g_q0[(nd0 + nd) * 64 + col] = v;
    }
    if (tid < 128) {
        int nd = tid >> 4, e = tid & 15;
        float a0 = 0, a1 = 0, a2 = 0;
        #pragma unroll
        for (int c = 0; c < 16; c++) {
            float w = Wq1[c * 16 + e];
            a0 += sg1[nd * 48 + c * 3 + 0] * w;
            a1 += sg1[nd * 48 + c * 3 + 1] * w;
            a2 += sg1[nd * 48 + c * 3 + 2] * w;
        }
        g_q1[(nd0 + nd) * 48 + e * 3 + 0] = a0;
        g_q1[(nd0 + nd) * 48 + e * 3 + 1] = a1;
        g_q1[(nd0 + nd) * 48 + e * 3 + 2] = a2;
    }
}

// ---------------- per-node neighbor transforms (per layer) ----------------
__global__ void __launch_bounds__(256) node_pre_kernel(
    const float* __restrict__ Wk00, const float* __restrict__ Wk10,
    const float* __restrict__ Wk01, const float* __restrict__ Wk11, const float* __restrict__ Wk11r,
    const float* __restrict__ Wv00, const float* __restrict__ Wv10,
    const float* __restrict__ Wv01, const float* __restrict__ Wv11, const float* __restrict__ Wv11r)
{
    __shared__ __align__(16) float sg0[NB * 64], sg1[NB * 48];
    int nd0 = blockIdx.x * NB;
    int tid = threadIdx.x;
    if (tid < 128) ((float4*)sg0)[tid] = ((const float4*)(g_g0 + nd0 * 64))[tid];
    else if (tid < 224) ((float4*)sg1)[tid - 128] = ((const float4*)(g_g1 + nd0 * 48))[tid - 128];
    __syncthreads();

    int nd = tid >> 5, c0 = (tid & 31) * 2;
    // A0 = g0 @ W00 and M10[m] = einsum(g1, W10), packed channel pairs
    #pragma unroll
    for (int side = 0; side < 2; side++) {
        const float* W00 = side ? Wv00 : Wk00;
        uint64_t acc = 0;
        #pragma unroll 8
        for (int d = 0; d < 64; d++)
            fma2(acc, *(const uint64_t*)(W00 + d * 64 + c0), dup2(sg0[nd * 64 + d]));
        *(uint64_t*)(g_A0 + (nd0 + nd) * 128 + side * 64 + c0) = acc;

        const float* W10 = side ? Wv10 : Wk10;
        #pragma unroll
        for (int m = 0; m < 3; m++) {
            uint64_t a = 0;
            #pragma unroll
            for (int c = 0; c < 16; c++)
                fma2(a, *(const uint64_t*)(W10 + c * 64 + c0), dup2(sg1[nd * 48 + c * 3 + m]));
            *(uint64_t*)(g_M10 + (nd0 + nd) * 384 + side * 192 + m * 64 + c0) = a;
        }
    }
    // S01 = g0 @ W01 : 2 sides x 8 nodes x 16 e = 256 outputs
    {
        int side = tid >> 7, rem = tid & 127;
        int nds = rem >> 4, e = rem & 15;
        const float* W01 = side ? Wv01 : Wk01;
        float acc = 0;
        #pragma unroll 8
        for (int d = 0; d < 64; d++) acc += sg0[nds * 64 + d] * W01[d * 16 + e];
        g_S01[(nd0 + nds) * 32 + side * 16 + e] = acc;
    }
    // T1 = einsum(g1, W11), Mr = einsum(g1, W11r) : 768 items each, layout [e*3+m]
    #pragma unroll
    for (int r = 0; r < 3; r++) {
        int item = r * 256 + tid;
        int side = (item >= 384) ? 1 : 0;
        int rem = item - side * 384;
        int nds = rem / 48, t = rem - nds * 48, e = t / 3, m = t - e * 3;
        const float* W11 = side ? Wv11 : Wk11;
        const float* W11r = side ? Wv11r : Wk11r;
        float a = 0, ar = 0;
        #pragma unroll
        for (int c = 0; c < 16; c++) {
            float gv = sg1[nds * 48 + c * 3 + m];
            a += gv * W11[c * 16 + e];
            ar += gv * W11r[c * 16 + e];
        }
        g_T1[(nd0 + nds) * 96 + side * 48 + t] = a;
        g_Mr[(nd0 + nds) * 96 + side * 48 + t] = ar;
    }
}

// ---------------- fused attention kernel (edge-light) ----------------
__global__ void __launch_bounds__(256) attn_kernel(
    const int* __restrict__ nbr,
    const float* __restrict__ Rw1, const float* __restrict__ Rb1,
    const float* __restrict__ Rw20, const float* __restrict__ Rw21,
    const float* __restrict__ Wo0, const float* __restrict__ Wo1)
{
    __shared__ int snbr[32];
    __shared__ __align__(16) float sGEO[128];   // [j][rx,ry,rz,dist]
    __shared__ __align__(16) float sRH[512];    // rh[j][16]
    __shared__ __align__(16) float sR0[2048];   // r0[j][64]
    __shared__ __align__(16) float sR1[512];    // r1[j][16]
    __shared__ __align__(16) float sV0[2048];   // v0[j][64]
    __shared__ __align__(16) float sK1[1536];   // k1[j][48]
    __shared__ __align__(16) float sV1[1536];   // v1[j][48]
    __shared__ __align__(16) float sQ0[64], sQ1[48], sLOG[128], sO[112];

    int bn = blockIdx.x;
    int b = bn >> 12;  // Nc = 4096
    int tid = threadIdx.x, wid = tid >> 5, lane = tid & 31;

    // ---- P0: neighbor ids, q0/q1, geometry, radial hidden ----
    if (tid < 32) snbr[tid] = b * Nc + nbr[bn * Kc + tid];
    else if (tid < 48) ((float4*)sQ0)[tid - 32] = ((const float4*)(g_q0 + bn * 64))[tid - 32];
    else if (tid < 60) ((float4*)sQ1)[tid - 48] = ((const float4*)(g_q1 + bn * 48))[tid - 48];
    else if (tid >= 128) {
        int t = tid - 128, j = t >> 2, c = t & 3;
        sGEO[t] = (c < 3) ? g_rhat[(bn * Kc + j) * 3 + c] : g_dist[bn * Kc + j];
    }
    #pragma unroll
    for (int r = 0; r < 2; r++) {
        int u = r * 256 + tid, j = u >> 4, c = u & 15;
        sRH[u] = gelu_t(g_dist[bn * Kc + j] * Rw1[c] + Rb1[c]);
    }
    __syncthreads();

    // ---- P2: r0 = rh @ Rw20 (packed), r1 = rh @ Rw21 ----
    {
        int j = tid >> 3, c8 = (tid & 7) * 8;
        uint64_t a0 = 0, a1 = 0, a2 = 0, a3 = 0;
        const float* rhp = sRH + j * 16;
        #pragma unroll
        for (int i = 0; i < 16; i++) {
            uint64_t h2 = dup2(rhp[i]);
            const ulonglong2* w = (const ulonglong2*)(Rw20 + i * 64 + c8);
            ulonglong2 w0 = w[0], w1 = w[1];
            fma2(a0, w0.x, h2); fma2(a1, w0.y, h2);
            fma2(a2, w1.x, h2); fma2(a3, w1.y, h2);
        }
        ((ulonglong2*)(sR0 + j * 64 + c8))[0] = make_ulonglong2(a0, a1);
        ((ulonglong2*)(sR0 + j * 64 + c8))[1] = make_ulonglong2(a2, a3);
    }
    #pragma unroll
    for (int r = 0; r < 2; r++) {
        int u = r * 256 + tid, j = u >> 4, e = u & 15;
        float acc = 0;
        #pragma unroll
        for (int i = 0; i < 16; i++) acc += sRH[j * 16 + i] * Rw21[i * 16 + e];
        sR1[u] = acc;
    }
    __syncthreads();

    // ---- P3: k0/v0 via gathered per-node transforms; logits0 / store v0 ----
    {
        int side = wid & 1;
        int jb = (wid >> 1) * 8;
        int c0 = lane * 2;
        const float* A0 = g_A0 + side * 64;
        const float* M10 = g_M10 + side * 192;
        float2 q0p = *(const float2*)(sQ0 + c0);
        float la[8];
        #pragma unroll
        for (int q = 0; q < 8; q++) {
            int j = jb + q;
            int gj = snbr[j];
            uint64_t acc = *(const uint64_t*)(A0 + gj * 128 + c0);
            #pragma unroll
            for (int m = 0; m < 3; m++) {
                uint64_t w2 = *(const uint64_t*)(M10 + gj * 384 + m * 64 + c0);
                fma2(acc, w2, dup2(sGEO[j * 4 + m]));
            }
            uint64_t res = mul2(acc, *(const uint64_t*)(sR0 + j * 64 + c0));
            if (side) {
                *(uint64_t*)(sV0 + j * 64 + c0) = res;
            } else {
                float2 k = unpack2(res);
                la[q] = q0p.x * k.x + q0p.y * k.y;
            }
        }
        if (!side) {
            #pragma unroll
            for (int o = 4; o > 0; o >>= 1) {
                #pragma unroll
                for (int q = 0; q < 8; q++)
                    la[q] += __shfl_xor_sync(0xffffffffu, la[q], o);
            }
            if ((lane & 7) == 0) {
                int h = lane >> 3;
                #pragma unroll
                for (int q = 0; q < 8; q++) sLOG[h * 32 + jb + q] = la[q];
            }
        }
    }

    // ---- P4: k1/v1 assembly: 1024 items (side, j, e), 3 m-components each ----
    #pragma unroll
    for (int r = 0; r < 4; r++) {
        int item = r * 256 + tid;
        int side = item >> 9, rem = item & 511;
        int j = rem >> 4, e = rem & 15;
        int gj = snbr[j];
        const float* Mr = g_Mr + gj * 96 + side * 48 + e * 3;
        float s11 = sGEO[j * 4 + 0] * Mr[0] + sGEO[j * 4 + 1] * Mr[1] + sGEO[j * 4 + 2] * Mr[2];
        float s = g_S01[gj * 32 + side * 16 + e] + s11;
        float r1e = sR1[j * 16 + e];
        const float* T1 = g_T1 + gj * 96 + side * 48 + e * 3;
        float* out = (side ? sV1 : sK1) + j * 48 + e * 3;
        #pragma unroll
        for (int m = 0; m < 3; m++)
            out[m] = (s * sGEO[j * 4 + m] + T1[m]) * r1e;
    }
    __syncthreads();

    // ---- P5: finalize logits with degree-1 term ----
    if (tid < 128) {
        int h = tid & 3, j = tid >> 2;
        float lg = 0.0f;
        #pragma unroll
        for (int t = 0; t < 12; t++)
            lg += sQ1[h * 12 + t] * sK1[j * 48 + h * 12 + t];
        sLOG[h * 32 + j] = (sLOG[h * 32 + j] + lg) * SCALEc;
    }
    __syncthreads();

    // ---- P6: softmax over neighbors ----
    if (tid < 32) {
        #pragma unroll
        for (int h = 0; h < 4; h++) {
            float x = sLOG[h * 32 + tid];
            float mx = x;
            #pragma unroll
            for (int o = 16; o > 0; o >>= 1) mx = fmaxf(mx, __shfl_xor_sync(0xffffffffu, mx, o));
            float ev = __expf(x - mx);
            float s = ev;
            #pragma unroll
            for (int o = 16; o > 0; o >>= 1) s += __shfl_xor_sync(0xffffffffu, s, o);
            sLOG[h * 32 + tid] = __fdividef(ev, s);
        }
    }
    __syncthreads();

    // ---- P7: weighted sum over neighbors ----
    if (tid < 112) {
        int h = (tid < 64) ? (tid >> 4) : ((tid - 64) / 12);
        float acc = 0.0f;
        #pragma unroll 8
        for (int j = 0; j < 32; j++) {
            float v = (tid < 64) ? sV0[j * 64 + tid] : sV1[j * 48 + (tid - 64)];
            acc += sLOG[h * 32 + j] * v;
        }
        sO[tid] = acc;
    }
    __syncthreads();

    // ---- P8: output projection + residual ----
    if (tid < 64) {
        float a = 0.0f;
        #pragma unroll 8
        for (int d = 0; d < 64; d++) a += sO[d] * Wo0[d * 64 + tid];
        g_f0[bn * 64 + tid] += a;
    } else if (tid < 112) {
        int t = tid - 64, e = t / 3, m = t - e * 3;
        float a = 0.0f;
        #pragma unroll
        for (int c = 0; c < 16; c++) a += sO[64 + c * 3 + m] * Wo1[c * 16 + e];
        g_f1[bn * 48 + t] += a;
    }
}

// ---------------- node-batched fused FF (+ next-layer prenorm + q) ----------------
__global__ void __launch_bounds__(256) ff_kernel(
    const float* __restrict__ F0w1, const float* __restrict__ F0w2,
    const float* __restrict__ F1w1, const float* __restrict__ F1w2,
    const float* __restrict__ Wq0n, const float* __restrict__ Wq1n)
{
    __shared__ __align__(16) float sf0[NB * 64], sf1[NB * 48];
    __shared__ __align__(16) float sg0[NB * 64], sg1[NB * 48];
    __shared__ __align__(16) float sh[NB * 256];
    __shared__ __align__(16) float su[NB * 192];
    __shared__ __align__(16) float sp[4 * NB * 64];
    int nd0 = blockIdx.x * NB;
    int tid = threadIdx.x, wid = tid >> 5, lane = tid & 31;

    if (tid < 128) ((float4*)sf0)[tid] = ((const float4*)(g_f0 + nd0 * 64))[tid];
    else if (tid < 224) ((float4*)sf1)[tid - 128] = ((const float4*)(g_f1 + nd0 * 48))[tid - 128];
    __syncthreads();

    {
        int nd = wid;
        float x0 = sf0[nd * 64 + lane], x1 = sf0[nd * 64 + 32 + lane];
        float y0 = sf1[nd * 48 + lane], y1 = (lane < 16) ? sf1[nd * 48 + 32 + lane] : 0.0f;
        float s = x0 + x1, s2 = x0 * x0 + x1 * x1, c2 = y0 * y0 + y1 * y1;
        #pragma unroll
        for (int o = 16; o > 0; o >>= 1) {
            s += __shfl_xor_sync(0xffffffffu, s, o);
            s2 += __shfl_xor_sync(0xffffffffu, s2, o);
            c2 += __shfl_xor_sync(0xffffffffu, c2, o);
        }
        float mu = s * (1.0f / 64.0f);
        float rsig = rsqrtf(s2 * (1.0f / 64.0f) - mu * mu + EPSc);
        float rms = rsqrtf(c2 * (1.0f / 16.0f) + EPSc);
        sg0[nd * 64 + lane] = (x0 - mu) * rsig;
        sg0[nd * 64 + 32 + lane] = (x1 - mu) * rsig;
        sg1[nd * 48 + lane] = y0 * rms;
        if (lane < 16) sg1[nd * 48 + 32 + lane] = y1 * rms;
    }
    __syncthreads();

    {
        uint64_t acc[4] = {0, 0, 0, 0};
        #pragma unroll 4
        for (int d4 = 0; d4 < 16; d4++) {
            float4 g[NB];
            #pragma unroll
            for (int nd = 0; nd < NB; nd++) g[nd] = ((const float4*)(sg0 + nd * 64))[d4];
            #pragma unroll
            for (int dd = 0; dd < 4; dd++) {
                uint64_t w2 = dup2(F0w1[(d4 * 4 + dd) * 256 + tid]);
                #pragma unroll
                for (int p = 0; p < 4; p++)
                    fma2(acc[p], w2, pack2(((const float*)&g[2 * p])[dd], ((const float*)&g[2 * p + 1])[dd]));
            }
        }
        #pragma unroll
        for (int p = 0; p < 4; p++) {
            float2 v = unpack2(acc[p]);
            sh[(2 * p) * 256 + tid] = gelu_t(v.x);
            sh[(2 * p + 1) * 256 + tid] = gelu_t(v.y);
        }
    }
    {
        int nd = tid >> 5, elo = tid & 31;
        float a0[3] = {0, 0, 0}, a1[3] = {0, 0, 0};
        #pragma unroll
        for (int c = 0; c < 16; c++) {
            float w0 = F1w1[c * 64 + elo], w1 = F1w1[c * 64 + elo + 32];
            float m0 = sg1[nd * 48 + c * 3 + 0];
            float m1 = sg1[nd * 48 + c * 3 + 1];
            float m2 = sg1[nd * 48 + c * 3 + 2];
            a0[0] += m0 * w0; a0[1] += m1 * w0; a0[2] += m2 * w0;
            a1[0] += m0 * w1; a1[1] += m1 * w1; a1[2] += m2 * w1;
        }
        float g0 = sigmoid_f(sqrtf(a0[0] * a0[0] + a0[1] * a0[1] + a0[2] * a0[2]));
        float g1v = sigmoid_f(sqrtf(a1[0] * a1[0] + a1[1] * a1[1] + a1[2] * a1[2]));
        #pragma unroll
        for (int m = 0; m < 3; m++) {
            su[nd * 192 + elo * 3 + m] = a0[m] * g0;
            su[nd * 192 + (elo + 32) * 3 + m] = a1[m] * g1v;
        }
    }
    __syncthreads();

    {
        int col = tid & 63, chunk = tid >> 6;
        uint64_t acc[4] = {0, 0, 0, 0};
        #pragma unroll 4
        for (int i4 = 0; i4 < 16; i4++) {
            float4 h[NB];
            #pragma unroll
            for (int nd = 0; nd < NB; nd++) h[nd] = ((const float4*)(sh + nd * 256))[chunk * 16 + i4];
            #pragma unroll
            for (int ii = 0; ii < 4; ii++) {
                uint64_t w2 = dup2(F0w2[(chunk * 64 + i4 * 4 + ii) * 64 + col]);
                #pragma unroll
                for (int p = 0; p < 4; p++)
                    fma2(acc[p], w2, pack2(((const float*)&h[2 * p])[ii], ((const float*)&h[2 * p + 1])[ii]));
            }
        }
        #pragma unroll
        for (int p = 0; p < 4; p++) {
            float2 v = unpack2(acc[p]);
            sp[(chunk * NB + 2 * p) * 64 + col] = v.x;
            sp[(chunk * NB + 2 * p + 1) * 64 + col] = v.y;
        }
    }
    __syncthreads();
    #pragma unroll
    for (int r = 0; r < 2; r++) {
        int o = r * 256 + tid;
        int nd = o >> 6, col = o & 63;
        float v = sf0[nd * 64 + col]
                + sp[nd * 64 + col] + sp[(NB + nd) * 64 + col]
                + sp[(2 * NB + nd) * 64 + col] + sp[(3 * NB + nd) * 64 + col];
        sf0[nd * 64 + col] = v;
        g_f0[(nd0 + nd) * 64 + col] = v;
    }
    if (tid < 128) {
        int nd = tid >> 4, f = tid & 15;
        float a0 = 0, a1 = 0, a2 = 0;
        #pragma unroll 8
        for (int e = 0; e < 64; e++) {
            float w = F1w2[e * 16 + f];
            a0 += su[nd * 192 + e * 3 + 0] * w;
            a1 += su[nd * 192 + e * 3 + 1] * w;
            a2 += su[nd * 192 + e * 3 + 2] * w;
        }
        float v0 = sf1[nd * 48 + f * 3 + 0] + a0;
        float v1 = sf1[nd * 48 + f * 3 + 1] + a1;
        float v2 = sf1[nd * 48 + f * 3 + 2] + a2;
        sf1[nd * 48 + f * 3 + 0] = v0; g_f1[(nd0 + nd) * 48 + f * 3 + 0] = v0;
        sf1[nd * 48 + f * 3 + 1] = v1; g_f1[(nd0 + nd) * 48 + f * 3 + 1] = v1;
        sf1[nd * 48 + f * 3 + 2] = v2; g_f1[(nd0 + nd) * 48 + f * 3 + 2] = v2;
    }

    if (Wq0n == nullptr) return;
    __syncthreads();

    {
        int nd = wid;
        float x0 = sf0[nd * 64 + lane], x1 = sf0[nd * 64 + 32 + lane];
        float y0 = sf1[nd * 48 + lane], y1 = (lane < 16) ? sf1[nd * 48 + 32 + lane] : 0.0f;
        float s = x0 + x1, s2 = x0 * x0 + x1 * x1, c2 = y0 * y0 + y1 * y1;
        #pragma unroll
        for (int o = 16; o > 0; o >>= 1) {
            s += __shfl_xor_sync(0xffffffffu, s, o);
            s2 += __shfl_xor_sync(0xffffffffu, s2, o);
            c2 += __shfl_xor_sync(0xffffffffu, c2, o);
        }
        float mu = s * (1.0f / 64.0f);
        float rsig = rsqrtf(s2 * (1.0f / 64.0f) - mu * mu + EPSc);
        float rms = rsqrtf(c2 * (1.0f / 16.0f) + EPSc);
        float a0 = (x0 - mu) * rsig, a1 = (x1 - mu) * rsig;
        sg0[nd * 64 + lane] = a0; sg0[nd * 64 + 32 + lane] = a1;
        g_g0[(nd0 + nd) * 64 + lane] = a0; g_g0[(nd0 + nd) * 64 + 32 + lane] = a1;
        float b0 = y0 * rms;
        sg1[nd * 48 + lane] = b0; g_g1[(nd0 + nd) * 48 + lane] = b0;
        if (lane < 16) {
            float b1 = y1 * rms;
            sg1[nd * 48 + 32 + lane] = b1; g_g1[(nd0 + nd) * 48 + 32 + lane] = b1;
        }
    }
    __syncthreads();

    {
        int col = tid & 63, chunk = tid >> 6;
        float acc[NB] = {0, 0, 0, 0, 0, 0, 0, 0};
        #pragma unroll
        for (int d4 = 0; d4 < 4; d4++) {
            float4 g[NB];
            #pragma unroll
            for (int nd = 0; nd < NB; nd++) g[nd] = ((const float4*)(sg0 + nd * 64))[chunk * 4 + d4];
            #pragma unroll
            for (int dd = 0; dd < 4; dd++) {
                float w = Wq0n[(chunk * 16 + d4 * 4 + dd) * 64 + col];
                #pragma unroll
                for (int nd = 0; nd < NB; nd++) acc[nd] += ((const float*)&g[nd])[dd] * w;
            }
        }
        #pragma unroll
        for (int nd = 0; nd < NB; nd++) sp[(chunk * NB + nd) * 64 + col] = acc[nd];
    }
    __syncthreads();
    #pragma unroll
    for (int r = 0; r < 2; r++) {
        int o = r * 256 + tid;
        int nd = o >> 6, col = o & 63;
        float v = sp[nd * 64 + col] + sp[(NB + nd) * 64 + col]
                + sp[(2 * NB + nd) * 64 + col] + sp[(3 * NB + nd) * 64 + col];
        g_q0[(nd0 + nd) * 64 + col] = v;
    }
    if (tid < 128) {
        int nd = tid >> 4, e = tid & 15;
        float a0 = 0, a1 = 0, a2 = 0;
        #pragma unroll
        for (int c = 0; c < 16; c++) {
            float w = Wq1n[c * 16 + e];
            a0 += sg1[nd * 48 + c * 3 + 0] * w;
            a1 += sg1[nd * 48 + c * 3 + 1] * w;
            a2 += sg1[nd * 48 + c * 3 + 2] * w;
        }
        g_q1[(nd0 + nd) * 48 + e * 3 + 0] = a0;
        g_q1[(nd0 + nd) * 48 + e * 3 + 1] = a1;
        g_q1[(nd0 + nd) * 48 + e * 3 + 2] = a2;
    }
}

// ---------------- concat to output ----------------
__global__ void concat_kernel(float* __restrict__ out) {
    int i = blockIdx.x * blockDim.x + threadIdx.x;
    if (i >= NN * 112) return;
    int bn = i / 112, c = i - bn * 112;
    out[i] = (c < 64) ? g_f0[bn * 64 + c] : g_f1[bn * 48 + (c - 64)];
}

// ---------------- launch ----------------
extern "C" void kernel_launch(void* const* d_in, const int* in_sizes, int n_in,
                              void* d_out, int out_size) {
    const float* f0 = (const float*)d_in[0];
    const float* f1 = (const float*)d_in[1];
    const float* coords = (const float*)d_in[2];
    const int* nbr = (const int*)d_in[3];
    const float* Wq0 = (const float*)d_in[4];
    const float* Wq1 = (const float*)d_in[5];
    const float* Wk00 = (const float*)d_in[6];
    const float* Wk10 = (const float*)d_in[7];
    const float* Wk01 = (const float*)d_in[8];
    const float* Wk11 = (const float*)d_in[9];
    const float* Wk11r = (const float*)d_in[10];
    const float* Wv00 = (const float*)d_in[11];
    const float* Wv10 = (const float*)d_in[12];
    const float* Wv01 = (const float*)d_in[13];
    const float* Wv11 = (const float*)d_in[14];
    const float* Wv11r = (const float*)d_in[15];
    const float* Rw1 = (const float*)d_in[16];
    const float* Rb1 = (const float*)d_in[17];
    const float* Rw20 = (const float*)d_in[18];
    const float* Rw21 = (const float*)d_in[19];
    const float* Wo0 = (const float*)d_in[20];
    const float* Wo1 = (const float*)d_in[21];
    const float* F0w1 = (const float*)d_in[22];
    const float* F0w2 = (const float*)d_in[23];
    const float* F1w1 = (const float*)d_in[24];
    const float* F1w2 = (const float*)d_in[25];
    float* out = (float*)d_out;

    geom_kernel<<<(NN * Kc + 255) / 256, 256>>>(coords, nbr);
    prenorm_q_init_kernel<<<NN / NB, 256>>>(f0, f1, Wq0, Wq1);

    for (int l = 0; l < 2; l++) {
        node_pre_kernel<<<NN / NB, 256>>>(
            Wk00 + l * 4096, Wk10 + l * 1024,
            Wk01 + l * 1024, Wk11 + l * 256, Wk11r + l * 256,
            Wv00 + l * 4096, Wv10 + l * 1024,
            Wv01 + l * 1024, Wv11 + l * 256, Wv11r + l * 256);
        attn_kernel<<<NN, 256>>>(
            nbr,
            Rw1 + l * 16, Rb1 + l * 16,
            Rw20 + l * 1024, Rw21 + l * 256,
            Wo0 + l * 4096, Wo1 + l * 256);
        const float* nq0 = (l == 0) ? (Wq0 + 64 * 64) : nullptr;
        const float* nq1 = (l == 0) ? (Wq1 + 16 * 16) : nullptr;
        ff_kernel<<<NN / NB, 256>>>(
            F0w1 + l * 64 * 256, F0w2 + l * 256 * 64,
            F1w1 + l * 16 * 64, F1w2 + l * 64 * 16,
            nq0, nq1);
    }
    concat_kernel<<<(NN * 112 + 255) / 256, 256>>>(out);
}

// round 13
// speedup vs baseline: 3.2417x; 1.1130x over previous
#include <cuda_runtime.h>
#include <math.h>
#include <stdint.h>

#define DEV_INLINE __device__ __forceinline__

// ---------------- problem constants ----------------
constexpr int Bc = 2, Nc = 4096, Kc = 32, NB = 8;
constexpr int NN = Bc * Nc;                 // 8192 nodes
constexpr float EPSc = 1e-6f;
constexpr float SCALEc = 0.18898223650461362f;  // 1/sqrt(28)

// ---------------- device scratch ----------------
__device__ float g_f0[NN * 64];
__device__ float g_f1[NN * 48];
__device__ float g_g0[NN * 64];
__device__ float g_g1[NN * 48];
__device__ float g_q0[NN * 64];
__device__ float g_q1[NN * 48];
__device__ float g_rhat[NN * Kc * 3];
__device__ float g_dist[NN * Kc];
// per-node precomputed neighbor transforms (side 0 = K, side 1 = V)
__device__ float g_A0[NN * 128];    // [node][side][64]   g0 @ W00
__device__ float g_M10[NN * 384];   // [node][side][m][64] einsum(g1, W10)
__device__ float g_S01[NN * 32];    // [node][side][16]   g0 @ W01
__device__ float g_T1[NN * 96];     // [node][side][e*3+m] einsum(g1, W11)
__device__ float g_Mr[NN * 96];     // [node][side][e*3+m] einsum(g1, W11r)

// ---------------- packed fp32x2 helpers ----------------
DEV_INLINE uint64_t pack2(float lo, float hi) {
    uint64_t r; asm("mov.b64 %0, {%1, %2};" : "=l"(r) : "f"(lo), "f"(hi)); return r;
}
DEV_INLINE uint64_t dup2(float v) {
    uint64_t r; asm("mov.b64 %0, {%1, %1};" : "=l"(r) : "f"(v)); return r;
}
DEV_INLINE void fma2(uint64_t& acc, uint64_t a, uint64_t b) {
    asm("fma.rn.f32x2 %0, %1, %2, %0;" : "+l"(acc) : "l"(a), "l"(b));
}
DEV_INLINE uint64_t mul2(uint64_t a, uint64_t b) {
    uint64_t r; asm("mul.rn.f32x2 %0, %1, %2;" : "=l"(r) : "l"(a), "l"(b)); return r;
}
DEV_INLINE float2 unpack2(uint64_t v) {
    float lo, hi; asm("mov.b64 {%0, %1}, %2;" : "=f"(lo), "=f"(hi) : "l"(v));
    return make_float2(lo, hi);
}
DEV_INLINE void cp_async16(uint32_t dst, const void* src) {
    asm volatile("cp.async.ca.shared.global [%0], [%1], 16;" :: "r"(dst), "l"(src));
}

DEV_INLINE float tanh_fast(float z) {
    z = fminf(fmaxf(z, -10.0f), 10.0f);
    float e = __expf(2.0f * z);
    return __fdividef(e - 1.0f, e + 1.0f);
}
DEV_INLINE float gelu_t(float x) {
    float x3 = x * x * x;
    return 0.5f * x * (1.0f + tanh_fast(0.7978845608028654f * (x + 0.044715f * x3)));
}
DEV_INLINE float sigmoid_f(float x) { return __fdividef(1.0f, 1.0f + __expf(-x)); }

// ---------------- geometry ----------------
__global__ void geom_kernel(const float* __restrict__ coords, const int* __restrict__ nbr) {
    int idx = blockIdx.x * blockDim.x + threadIdx.x;
    if (idx >= NN * Kc) return;
    int bn = idx / Kc;
    int b = bn / Nc;
    int gi = b * Nc + nbr[idx];
    float dx = coords[gi * 3 + 0] - coords[bn * 3 + 0];
    float dy = coords[gi * 3 + 1] - coords[bn * 3 + 1];
    float dz = coords[gi * 3 + 2] - coords[bn * 3 + 2];
    float d = sqrtf(dx * dx + dy * dy + dz * dz);
    g_dist[idx] = d;
    float inv = 1.0f / (d + EPSc);
    g_rhat[idx * 3 + 0] = dx * inv;
    g_rhat[idx * 3 + 1] = dy * inv;
    g_rhat[idx * 3 + 2] = dz * inv;
}

// ---------------- init: copy f, prenorm, q0/q1 for layer 0 ----------------
__global__ void __launch_bounds__(256) prenorm_q_init_kernel(
    const float* __restrict__ f0in, const float* __restrict__ f1in,
    const float* __restrict__ Wq0, const float* __restrict__ Wq1)
{
    __shared__ __align__(16) float sf0[NB * 64], sf1[NB * 48];
    __shared__ __align__(16) float sg0[NB * 64], sg1[NB * 48];
    __shared__ __align__(16) float sp[4 * NB * 64];
    int nd0 = blockIdx.x * NB;
    int tid = threadIdx.x, wid = tid >> 5, lane = tid & 31;

    if (tid < 128) {
        float4 v = ((const float4*)(f0in + nd0 * 64))[tid];
        ((float4*)sf0)[tid] = v;
        ((float4*)(g_f0 + nd0 * 64))[tid] = v;
    } else {
        int t = tid - 128;
        if (t < 96) {
            float4 v = ((const float4*)(f1in + nd0 * 48))[t];
            ((float4*)sf1)[t] = v;
            ((float4*)(g_f1 + nd0 * 48))[t] = v;
        }
    }
    __syncthreads();

    {
        int nd = wid;
        float x0 = sf0[nd * 64 + lane], x1 = sf0[nd * 64 + 32 + lane];
        float y0 = sf1[nd * 48 + lane], y1 = (lane < 16) ? sf1[nd * 48 + 32 + lane] : 0.0f;
        float s = x0 + x1, s2 = x0 * x0 + x1 * x1, c2 = y0 * y0 + y1 * y1;
        #pragma unroll
        for (int o = 16; o > 0; o >>= 1) {
            s += __shfl_xor_sync(0xffffffffu, s, o);
            s2 += __shfl_xor_sync(0xffffffffu, s2, o);
            c2 += __shfl_xor_sync(0xffffffffu, c2, o);
        }
        float mu = s * (1.0f / 64.0f);
        float rsig = rsqrtf(s2 * (1.0f / 64.0f) - mu * mu + EPSc);
        float rms = rsqrtf(c2 * (1.0f / 16.0f) + EPSc);
        float a0 = (x0 - mu) * rsig, a1 = (x1 - mu) * rsig;
        sg0[nd * 64 + lane] = a0; sg0[nd * 64 + 32 + lane] = a1;
        g_g0[(nd0 + nd) * 64 + lane] = a0; g_g0[(nd0 + nd) * 64 + 32 + lane] = a1;
        float b0 = y0 * rms;
        sg1[nd * 48 + lane] = b0; g_g1[(nd0 + nd) * 48 + lane] = b0;
        if (lane < 16) {
            float b1 = y1 * rms;
            sg1[nd * 48 + 32 + lane] = b1; g_g1[(nd0 + nd) * 48 + 32 + lane] = b1;
        }
    }
    __syncthreads();

    {
        int col = tid & 63, chunk = tid >> 6;
        float acc[NB] = {0, 0, 0, 0, 0, 0, 0, 0};
        #pragma unroll
        for (int d4 = 0; d4 < 4; d4++) {
            float4 g[NB];
            #pragma unroll
            for (int nd = 0; nd < NB; nd++) g[nd] = ((const float4*)(sg0 + nd * 64))[chunk * 4 + d4];
            #pragma unroll
            for (int dd = 0; dd < 4; dd++) {
                float w = Wq0[(chunk * 16 + d4 * 4 + dd) * 64 + col];
                #pragma unroll
                for (int nd = 0; nd < NB; nd++) acc[nd] += ((const float*)&g[nd])[dd] * w;
            }
        }
        #pragma unroll
        for (int nd = 0; nd < NB; nd++) sp[(chunk * NB + nd) * 64 + col] = acc[nd];
    }
    __syncthreads();
    #pragma unroll
    for (int r = 0; r < 2; r++) {
        int o = r * 256 + tid;
        int nd = o >> 6, col = o & 63;
        float v = sp[nd * 64 + col] + sp[(NB + nd) * 64 + col]
                + sp[(2 * NB + nd) * 64 + col] + sp[(3 * NB + nd) * 64 + col];
        g_q0[(nd0 + nd) * 64 + col] = v;
    }
    if (tid < 128) {
        int nd = tid >> 4, e = tid & 15;
        float a0 = 0, a1 = 0, a2 = 0;
        #pragma unroll
        for (int c = 0; c < 16; c++) {
            float w = Wq1[c * 16 + e];
            a0 += sg1[nd * 48 + c * 3 + 0] * w;
            a1 += sg1[nd * 48 + c * 3 + 1] * w;
            a2 += sg1[nd * 48 + c * 3 + 2] * w;
        }
        g_q1[(nd0 + nd) * 48 + e * 3 + 0] = a0;
        g_q1[(nd0 + nd) * 48 + e * 3 + 1] = a1;
        g_q1[(nd0 + nd) * 48 + e * 3 + 2] = a2;
    }
}

// ---------------- per-node neighbor transforms (per layer) ----------------
__global__ void __launch_bounds__(256) node_pre_kernel(
    const float* __restrict__ Wk00, const float* __restrict__ Wk10,
    const float* __restrict__ Wk01, const float* __restrict__ Wk11, const float* __restrict__ Wk11r,
    const float* __restrict__ Wv00, const float* __restrict__ Wv10,
    const float* __restrict__ Wv01, const float* __restrict__ Wv11, const float* __restrict__ Wv11r)
{
    __shared__ __align__(16) float sg0[NB * 64], sg1[NB * 48];
    int nd0 = blockIdx.x * NB;
    int tid = threadIdx.x;
    if (tid < 128) ((float4*)sg0)[tid] = ((const float4*)(g_g0 + nd0 * 64))[tid];
    else if (tid < 224) ((float4*)sg1)[tid - 128] = ((const float4*)(g_g1 + nd0 * 48))[tid - 128];
    __syncthreads();

    int nd = tid >> 5, c0 = (tid & 31) * 2;
    #pragma unroll
    for (int side = 0; side < 2; side++) {
        const float* W00 = side ? Wv00 : Wk00;
        uint64_t acc = 0;
        #pragma unroll 8
        for (int d = 0; d < 64; d++)
            fma2(acc, *(const uint64_t*)(W00 + d * 64 + c0), dup2(sg0[nd * 64 + d]));
        *(uint64_t*)(g_A0 + (nd0 + nd) * 128 + side * 64 + c0) = acc;

        const float* W10 = side ? Wv10 : Wk10;
        #pragma unroll
        for (int m = 0; m < 3; m++) {
            uint64_t a = 0;
            #pragma unroll
            for (int c = 0; c < 16; c++)
                fma2(a, *(const uint64_t*)(W10 + c * 64 + c0), dup2(sg1[nd * 48 + c * 3 + m]));
            *(uint64_t*)(g_M10 + (nd0 + nd) * 384 + side * 192 + m * 64 + c0) = a;
        }
    }
    {
        int side = tid >> 7, rem = tid & 127;
        int nds = rem >> 4, e = rem & 15;
        const float* W01 = side ? Wv01 : Wk01;
        float acc = 0;
        #pragma unroll 8
        for (int d = 0; d < 64; d++) acc += sg0[nds * 64 + d] * W01[d * 16 + e];
        g_S01[(nd0 + nds) * 32 + side * 16 + e] = acc;
    }
    #pragma unroll
    for (int r = 0; r < 3; r++) {
        int item = r * 256 + tid;
        int side = (item >= 384) ? 1 : 0;
        int rem = item - side * 384;
        int nds = rem / 48, t = rem - nds * 48, e = t / 3, m = t - e * 3;
        const float* W11 = side ? Wv11 : Wk11;
        const float* W11r = side ? Wv11r : Wk11r;
        float a = 0, ar = 0;
        #pragma unroll
        for (int c = 0; c < 16; c++) {
            float gv = sg1[nds * 48 + c * 3 + m];
            a += gv * W11[c * 16 + e];
            ar += gv * W11r[c * 16 + e];
        }
        g_T1[(nd0 + nds) * 96 + side * 48 + t] = a;
        g_Mr[(nd0 + nds) * 96 + side * 48 + t] = ar;
    }
}

// ---------------- fused attention kernel (edge-light, cp.async staged) ----------------
// dynamic smem layout (floats)
constexpr int SMR = 0;           // [side][j][48]  3072
constexpr int ST1 = 3072;        // [side][j][48]  3072
constexpr int SS01 = 6144;       // [side][j][16]  1024
constexpr int SV0 = 7168;        // [j][64]        2048
constexpr int SK1 = 9216;        // [j][48]        1536
constexpr int SV1 = 10752;       // [j][48]        1536
constexpr int SRH = 12288;       // [j][16]        512
constexpr int SR1 = 12800;       // [j][16]        512
constexpr int SGEO = 13312;      // [j][4]         128
constexpr int SQ0 = 13440;       // 64
constexpr int SQ1 = 13504;       // 48
constexpr int SLOG = 13552;      // 128
constexpr int SO = 13680;        // 112
constexpr int SNBR = 13792;      // 32 (int)
constexpr int ATT_FLOATS = 13824;
constexpr int ATT_SMEM = ATT_FLOATS * 4;   // 55296 B

__global__ void __launch_bounds__(256, 4) attn_kernel(
    const int* __restrict__ nbr,
    const float* __restrict__ Rw1, const float* __restrict__ Rb1,
    const float* __restrict__ Rw20, const float* __restrict__ Rw21,
    const float* __restrict__ Wo0, const float* __restrict__ Wo1)
{
    extern __shared__ float sm[];
    int bn = blockIdx.x;
    int b = bn >> 12;  // Nc = 4096
    int tid = threadIdx.x, wid = tid >> 5, lane = tid & 31;
    uint32_t smb = (uint32_t)__cvta_generic_to_shared(sm);

    // ---- P0a: stage Mr/T1/S01 via cp.async (1792 16B chunks, 7/thread) ----
    {
        int base_edge = bn * Kc;
        #pragma unroll
        for (int cc = 0; cc < 7; cc++) {
            int c = cc * 256 + tid;
            const float* src;
            int dstf;
            if (c < 768) {
                int side = (c >= 384) ? 1 : 0;
                int rem = c - side * 384;
                int j = rem / 12, off = rem - j * 12;
                int gj = b * Nc + nbr[base_edge + j];
                src = g_Mr + gj * 96 + side * 48 + off * 4;
                dstf = SMR + side * 1536 + j * 48 + off * 4;
            } else if (c < 1536) {
                int c1 = c - 768;
                int side = (c1 >= 384) ? 1 : 0;
                int rem = c1 - side * 384;
                int j = rem / 12, off = rem - j * 12;
                int gj = b * Nc + nbr[base_edge + j];
                src = g_T1 + gj * 96 + side * 48 + off * 4;
                dstf = ST1 + side * 1536 + j * 48 + off * 4;
            } else {
                int c2 = c - 1536;
                int side = c2 >> 7;
                int rem = c2 & 127;
                int j = rem >> 2, off = rem & 3;
                int gj = b * Nc + nbr[base_edge + j];
                src = g_S01 + gj * 32 + side * 16 + off * 4;
                dstf = SS01 + side * 512 + j * 16 + off * 4;
            }
            cp_async16(smb + dstf * 4, src);
        }
        asm volatile("cp.async.commit_group;");
    }

    // ---- P0b: neighbor ids, q0/q1, geometry ----
    if (tid < 32) ((int*)(sm + SNBR))[tid] = b * Nc + nbr[bn * Kc + tid];
    else if (tid < 48) ((float4*)(sm + SQ0))[tid - 32] = ((const float4*)(g_q0 + bn * 64))[tid - 32];
    else if (tid < 60) ((float4*)(sm + SQ1))[tid - 48] = ((const float4*)(g_q1 + bn * 48))[tid - 48];
    else if (tid >= 128) {
        int t = tid - 128, j = t >> 2, c = t & 3;
        sm[SGEO + t] = (c < 3) ? g_rhat[(bn * Kc + j) * 3 + c] : g_dist[bn * Kc + j];
    }
    // ---- P0c: radial hidden rh (512 items) ----
    #pragma unroll
    for (int r = 0; r < 2; r++) {
        int u = r * 256 + tid, j = u >> 4, c = u & 15;
        sm[SRH + u] = gelu_t(g_dist[bn * Kc + j] * Rw1[c] + Rb1[c]);
    }
    __syncthreads();

    // ---- P1: r1 = rh @ Rw21 (512 items; consumed by P4 after next sync) ----
    #pragma unroll
    for (int r = 0; r < 2; r++) {
        int u = r * 256 + tid, j = u >> 4, e = u & 15;
        float acc = 0;
        #pragma unroll
        for (int i = 0; i < 16; i++) acc += sm[SRH + j * 16 + i] * Rw21[i * 16 + e];
        sm[SR1 + u] = acc;
    }

    // ---- P3: k0/v0 with software pipelining; r0 computed inline per warp ----
    {
        int side = wid & 1;
        int jb = (wid >> 1) * 8;
        int c0 = lane * 2;
        const float* A0g = g_A0 + side * 64;
        const float* M10g = g_M10 + side * 192;
        const int* snbr = (const int*)(sm + SNBR);
        float2 q0p = *(const float2*)(sm + SQ0 + c0);
        float la[8];
        #pragma unroll
        for (int batch = 0; batch < 2; batch++) {
            int q4 = batch * 4;
            uint64_t a0v[4], m0v[4], m1v[4], m2v[4];
            #pragma unroll
            for (int q = 0; q < 4; q++) {
                int gj = snbr[jb + q4 + q];
                a0v[q] = *(const uint64_t*)(A0g + gj * 128 + c0);
                m0v[q] = *(const uint64_t*)(M10g + gj * 384 + c0);
                m1v[q] = *(const uint64_t*)(M10g + gj * 384 + 64 + c0);
                m2v[q] = *(const uint64_t*)(M10g + gj * 384 + 128 + c0);
            }
            // r0 for this batch (overlaps the in-flight gathers)
            uint64_t r0v[4] = {0, 0, 0, 0};
            #pragma unroll
            for (int i = 0; i < 16; i++) {
                uint64_t w2 = *(const uint64_t*)(Rw20 + i * 64 + c0);
                #pragma unroll
                for (int q = 0; q < 4; q++)
                    fma2(r0v[q], w2, dup2(sm[SRH + (jb + q4 + q) * 16 + i]));
            }
            #pragma unroll
            for (int q = 0; q < 4; q++) {
                int j = jb + q4 + q;
                uint64_t acc = a0v[q];
                fma2(acc, m0v[q], dup2(sm[SGEO + j * 4 + 0]));
                fma2(acc, m1v[q], dup2(sm[SGEO + j * 4 + 1]));
                fma2(acc, m2v[q], dup2(sm[SGEO + j * 4 + 2]));
                uint64_t res = mul2(acc, r0v[q]);
                if (side) {
                    *(uint64_t*)(sm + SV0 + j * 64 + c0) = res;
                } else {
                    float2 k = unpack2(res);
                    la[q4 + q] = q0p.x * k.x + q0p.y * k.y;
                }
            }
        }
        if (!side) {
            #pragma unroll
            for (int o = 4; o > 0; o >>= 1) {
                #pragma unroll
                for (int q = 0; q < 8; q++)
                    la[q] += __shfl_xor_sync(0xffffffffu, la[q], o);
            }
            if ((lane & 7) == 0) {
                int h = lane >> 3;
                #pragma unroll
                for (int q = 0; q < 8; q++) sm[SLOG + h * 32 + jb + q] = la[q];
            }
        }
    }
    asm volatile("cp.async.wait_group 0;" ::: "memory");
    __syncthreads();

    // ---- P4: k1/v1 assembly from staged smem ----
    #pragma unroll
    for (int r = 0; r < 4; r++) {
        int item = r * 256 + tid;
        int side = item >> 9, rem = item & 511;
        int j = rem >> 4, e = rem & 15;
        const float* Mr = sm + SMR + side * 1536 + j * 48 + e * 3;
        float rx = sm[SGEO + j * 4 + 0], ry = sm[SGEO + j * 4 + 1], rz = sm[SGEO + j * 4 + 2];
        float s11 = rx * Mr[0] + ry * Mr[1] + rz * Mr[2];
        float s = sm[SS01 + side * 512 + j * 16 + e] + s11;
        float r1e = sm[SR1 + j * 16 + e];
        const float* T1 = sm + ST1 + side * 1536 + j * 48 + e * 3;
        float* out = sm + (side ? SV1 : SK1) + j * 48 + e * 3;
        out[0] = (s * rx + T1[0]) * r1e;
        out[1] = (s * ry + T1[1]) * r1e;
        out[2] = (s * rz + T1[2]) * r1e;
    }
    __syncthreads();

    // ---- P5: finalize logits with degree-1 term ----
    if (tid < 128) {
        int h = tid & 3, j = tid >> 2;
        float lg = 0.0f;
        #pragma unroll
        for (int t = 0; t < 12; t++)
            lg += sm[SQ1 + h * 12 + t] * sm[SK1 + j * 48 + h * 12 + t];
        sm[SLOG + h * 32 + j] = (sm[SLOG + h * 32 + j] + lg) * SCALEc;
    }
    __syncthreads();

    // ---- P6: softmax over neighbors ----
    if (tid < 32) {
        #pragma unroll
        for (int h = 0; h < 4; h++) {
            float x = sm[SLOG + h * 32 + tid];
            float mx = x;
            #pragma unroll
            for (int o = 16; o > 0; o >>= 1) mx = fmaxf(mx, __shfl_xor_sync(0xffffffffu, mx, o));
            float ev = __expf(x - mx);
            float s = ev;
            #pragma unroll
            for (int o = 16; o > 0; o >>= 1) s += __shfl_xor_sync(0xffffffffu, s, o);
            sm[SLOG + h * 32 + tid] = __fdividef(ev, s);
        }
    }
    __syncthreads();

    // ---- P7: weighted sum over neighbors ----
    if (tid < 112) {
        int h = (tid < 64) ? (tid >> 4) : ((tid - 64) / 12);
        float acc = 0.0f;
        #pragma unroll 8
        for (int j = 0; j < 32; j++) {
            float v = (tid < 64) ? sm[SV0 + j * 64 + tid] : sm[SV1 + j * 48 + (tid - 64)];
            acc += sm[SLOG + h * 32 + j] * v;
        }
        sm[SO + tid] = acc;
    }
    __syncthreads();

    // ---- P8: output projection + residual ----
    if (tid < 64) {
        float a = 0.0f;
        #pragma unroll 8
        for (int d = 0; d < 64; d++) a += sm[SO + d] * Wo0[d * 64 + tid];
        g_f0[bn * 64 + tid] += a;
    } else if (tid < 112) {
        int t = tid - 64, e = t / 3, m = t - e * 3;
        float a = 0.0f;
        #pragma unroll
        for (int c = 0; c < 16; c++) a += sm[SO + 64 + c * 3 + m] * Wo1[c * 16 + e];
        g_f1[bn * 48 + t] += a;
    }
}

// ---------------- node-batched fused FF (+ next-layer prenorm + q) ----------------
__global__ void __launch_bounds__(256) ff_kernel(
    const float* __restrict__ F0w1, const float* __restrict__ F0w2,
    const float* __restrict__ F1w1, const float* __restrict__ F1w2,
    const float* __restrict__ Wq0n, const float* __restrict__ Wq1n)
{
    __shared__ __align__(16) float sf0[NB * 64], sf1[NB * 48];
    __shared__ __align__(16) float sg0[NB * 64], sg1[NB * 48];
    __shared__ __align__(16) float sh[NB * 256];
    __shared__ __align__(16) float su[NB * 192];
    __shared__ __align__(16) float sp[4 * NB * 64];
    int nd0 = blockIdx.x * NB;
    int tid = threadIdx.x, wid = tid >> 5, lane = tid & 31;

    if (tid < 128) ((float4*)sf0)[tid] = ((const float4*)(g_f0 + nd0 * 64))[tid];
    else if (tid < 224) ((float4*)sf1)[tid - 128] = ((const float4*)(g_f1 + nd0 * 48))[tid - 128];
    __syncthreads();

    {
        int nd = wid;
        float x0 = sf0[nd * 64 + lane], x1 = sf0[nd * 64 + 32 + lane];
        float y0 = sf1[nd * 48 + lane], y1 = (lane < 16) ? sf1[nd * 48 + 32 + lane] : 0.0f;
        float s = x0 + x1, s2 = x0 * x0 + x1 * x1, c2 = y0 * y0 + y1 * y1;
        #pragma unroll
        for (int o = 16; o > 0; o >>= 1) {
            s += __shfl_xor_sync(0xffffffffu, s, o);
            s2 += __shfl_xor_sync(0xffffffffu, s2, o);
            c2 += __shfl_xor_sync(0xffffffffu, c2, o);
        }
        float mu = s * (1.0f / 64.0f);
        float rsig = rsqrtf(s2 * (1.0f / 64.0f) - mu * mu + EPSc);
        float rms = rsqrtf(c2 * (1.0f / 16.0f) + EPSc);
        sg0[nd * 64 + lane] = (x0 - mu) * rsig;
        sg0[nd * 64 + 32 + lane] = (x1 - mu) * rsig;
        sg1[nd * 48 + lane] = y0 * rms;
        if (lane < 16) sg1[nd * 48 + 32 + lane] = y1 * rms;
    }
    __syncthreads();

    {
        uint64_t acc[4] = {0, 0, 0, 0};
        #pragma unroll 4
        for (int d4 = 0; d4 < 16; d4++) {
            float4 g[NB];
            #pragma unroll
            for (int nd = 0; nd < NB; nd++) g[nd] = ((const float4*)(sg0 + nd * 64))[d4];
            #pragma unroll
            for (int dd = 0; dd < 4; dd++) {
                uint64_t w2 = dup2(F0w1[(d4 * 4 + dd) * 256 + tid]);
                #pragma unroll
                for (int p = 0; p < 4; p++)
                    fma2(acc[p], w2, pack2(((const float*)&g[2 * p])[dd], ((const float*)&g[2 * p + 1])[dd]));
            }
        }
        #pragma unroll
        for (int p = 0; p < 4; p++) {
            float2 v = unpack2(acc[p]);
            sh[(2 * p) * 256 + tid] = gelu_t(v.x);
            sh[(2 * p + 1) * 256 + tid] = gelu_t(v.y);
        }
    }
    {
        int nd = tid >> 5, elo = tid & 31;
        float a0[3] = {0, 0, 0}, a1[3] = {0, 0, 0};
        #pragma unroll
        for (int c = 0; c < 16; c++) {
            float w0 = F1w1[c * 64 + elo], w1 = F1w1[c * 64 + elo + 32];
            float m0 = sg1[nd * 48 + c * 3 + 0];
            float m1 = sg1[nd * 48 + c * 3 + 1];
            float m2 = sg1[nd * 48 + c * 3 + 2];
            a0[0] += m0 * w0; a0[1] += m1 * w0; a0[2] += m2 * w0;
            a1[0] += m0 * w1; a1[1] += m1 * w1; a1[2] += m2 * w1;
        }
        float g0 = sigmoid_f(sqrtf(a0[0] * a0[0] + a0[1] * a0[1] + a0[2] * a0[2]));
        float g1v = sigmoid_f(sqrtf(a1[0] * a1[0] + a1[1] * a1[1] + a1[2] * a1[2]));
        #pragma unroll
        for (int m = 0; m < 3; m++) {
            su[nd * 192 + elo * 3 + m] = a0[m] * g0;
            su[nd * 192 + (elo + 32) * 3 + m] = a1[m] * g1v;
        }
    }
    __syncthreads();

    {
        int col = tid & 63, chunk = tid >> 6;
        uint64_t acc[4] = {0, 0, 0, 0};
        #pragma unroll 4
        for (int i4 = 0; i4 < 16; i4++) {
            float4 h[NB];
            #pragma unroll
            for (int nd = 0; nd < NB; nd++) h[nd] = ((const float4*)(sh + nd * 256))[chunk * 16 + i4];
            #pragma unroll
            for (int ii = 0; ii < 4; ii++) {
                uint64_t w2 = dup2(F0w2[(chunk * 64 + i4 * 4 + ii) * 64 + col]);
                #pragma unroll
                for (int p = 0; p < 4; p++)
                    fma2(acc[p], w2, pack2(((const float*)&h[2 * p])[ii], ((const float*)&h[2 * p + 1])[ii]));
            }
        }
        #pragma unroll
        for (int p = 0; p < 4; p++) {
            float2 v = unpack2(acc[p]);
            sp[(chunk * NB + 2 * p) * 64 + col] = v.x;
            sp[(chunk * NB + 2 * p + 1) * 64 + col] = v.y;
        }
    }
    __syncthreads();
    #pragma unroll
    for (int r = 0; r < 2; r++) {
        int o = r * 256 + tid;
        int nd = o >> 6, col = o & 63;
        float v = sf0[nd * 64 + col]
                + sp[nd * 64 + col] + sp[(NB + nd) * 64 + col]
                + sp[(2 * NB + nd) * 64 + col] + sp[(3 * NB + nd) * 64 + col];
        sf0[nd * 64 + col] = v;
        g_f0[(nd0 + nd) * 64 + col] = v;
    }
    if (tid < 128) {
        int nd = tid >> 4, f = tid & 15;
        float a0 = 0, a1 = 0, a2 = 0;
        #pragma unroll 8
        for (int e = 0; e < 64; e++) {
            float w = F1w2[e * 16 + f];
            a0 += su[nd * 192 + e * 3 + 0] * w;
            a1 += su[nd * 192 + e * 3 + 1] * w;
            a2 += su[nd * 192 + e * 3 + 2] * w;
        }
        float v0 = sf1[nd * 48 + f * 3 + 0] + a0;
        float v1 = sf1[nd * 48 + f * 3 + 1] + a1;
        float v2 = sf1[nd * 48 + f * 3 + 2] + a2;
        sf1[nd * 48 + f * 3 + 0] = v0; g_f1[(nd0 + nd) * 48 + f * 3 + 0] = v0;
        sf1[nd * 48 + f * 3 + 1] = v1; g_f1[(nd0 + nd) * 48 + f * 3 + 1] = v1;
        sf1[nd * 48 + f * 3 + 2] = v2; g_f1[(nd0 + nd) * 48 + f * 3 + 2] = v2;
    }

    if (Wq0n == nullptr) return;
    __syncthreads();

    {
        int nd = wid;
        float x0 = sf0[nd * 64 + lane], x1 = sf0[nd * 64 + 32 + lane];
        float y0 = sf1[nd * 48 + lane], y1 = (lane < 16) ? sf1[nd * 48 + 32 + lane] : 0.0f;
        float s = x0 + x1, s2 = x0 * x0 + x1 * x1, c2 = y0 * y0 + y1 * y1;
        #pragma unroll
        for (int o = 16; o > 0; o >>= 1) {
            s += __shfl_xor_sync(0xffffffffu, s, o);
            s2 += __shfl_xor_sync(0xffffffffu, s2, o);
            c2 += __shfl_xor_sync(0xffffffffu, c2, o);
        }
        float mu = s * (1.0f / 64.0f);
        float rsig = rsqrtf(s2 * (1.0f / 64.0f) - mu * mu + EPSc);
        float rms = rsqrtf(c2 * (1.0f / 16.0f) + EPSc);
        float a0 = (x0 - mu) * rsig, a1 = (x1 - mu) * rsig;
        sg0[nd * 64 + lane] = a0; sg0[nd * 64 + 32 + lane] = a1;
        g_g0[(nd0 + nd) * 64 + lane] = a0; g_g0[(nd0 + nd) * 64 + 32 + lane] = a1;
        float b0 = y0 * rms;
        sg1[nd * 48 + lane] = b0; g_g1[(nd0 + nd) * 48 + lane] = b0;
        if (lane < 16) {
            float b1 = y1 * rms;
            sg1[nd * 48 + 32 + lane] = b1; g_g1[(nd0 + nd) * 48 + 32 + lane] = b1;
        }
    }
    __syncthreads();

    {
        int col = tid & 63, chunk = tid >> 6;
        float acc[NB] = {0, 0, 0, 0, 0, 0, 0, 0};
        #pragma unroll
        for (int d4 = 0; d4 < 4; d4++) {
            float4 g[NB];
            #pragma unroll
            for (int nd = 0; nd < NB; nd++) g[nd] = ((const float4*)(sg0 + nd * 64))[chunk * 4 + d4];
            #pragma unroll
            for (int dd = 0; dd < 4; dd++) {
                float w = Wq0n[(chunk * 16 + d4 * 4 + dd) * 64 + col];
                #pragma unroll
                for (int nd = 0; nd < NB; nd++) acc[nd] += ((const float*)&g[nd])[dd] * w;
            }
        }
        #pragma unroll
        for (int nd = 0; nd < NB; nd++) sp[(chunk * NB + nd) * 64 + col] = acc[nd];
    }
    __syncthreads();
    #pragma unroll
    for (int r = 0; r < 2; r++) {
        int o = r * 256 + tid;
        int nd = o >> 6, col = o & 63;
        float v = sp[nd * 64 + col] + sp[(NB + nd) * 64 + col]
                + sp[(2 * NB + nd) * 64 + col] + sp[(3 * NB + nd) * 64 + col];
        g_q0[(nd0 + nd) * 64 + col] = v;
    }
    if (tid < 128) {
        int nd = tid >> 4, e = tid & 15;
        float a0 = 0, a1 = 0, a2 = 0;
        #pragma unroll
        for (int c = 0; c < 16; c++) {
            float w = Wq1n[c * 16 + e];
            a0 += sg1[nd * 48 + c * 3 + 0] * w;
            a1 += sg1[nd * 48 + c * 3 + 1] * w;
            a2 += sg1[nd * 48 + c * 3 + 2] * w;
        }
        g_q1[(nd0 + nd) * 48 + e * 3 + 0] = a0;
        g_q1[(nd0 + nd) * 48 + e * 3 + 1] = a1;
        g_q1[(nd0 + nd) * 48 + e * 3 + 2] = a2;
    }
}

// ---------------- concat to output ----------------
__global__ void concat_kernel(float* __restrict__ out) {
    int i = blockIdx.x * blockDim.x + threadIdx.x;
    if (i >= NN * 112) return;
    int bn = i / 112, c = i - bn * 112;
    out[i] = (c < 64) ? g_f0[bn * 64 + c] : g_f1[bn * 48 + (c - 64)];
}

// ---------------- launch ----------------
extern "C" void kernel_launch(void* const* d_in, const int* in_sizes, int n_in,
                              void* d_out, int out_size) {
    const float* f0 = (const float*)d_in[0];
    const float* f1 = (const float*)d_in[1];
    const float* coords = (const float*)d_in[2];
    const int* nbr = (const int*)d_in[3];
    const float* Wq0 = (const float*)d_in[4];
    const float* Wq1 = (const float*)d_in[5];
    const float* Wk00 = (const float*)d_in[6];
    const float* Wk10 = (const float*)d_in[7];
    const float* Wk01 = (const float*)d_in[8];
    const float* Wk11 = (const float*)d_in[9];
    const float* Wk11r = (const float*)d_in[10];
    const float* Wv00 = (const float*)d_in[11];
    const float* Wv10 = (const float*)d_in[12];
    const float* Wv01 = (const float*)d_in[13];
    const float* Wv11 = (const float*)d_in[14];
    const float* Wv11r = (const float*)d_in[15];
    const float* Rw1 = (const float*)d_in[16];
    const float* Rb1 = (const float*)d_in[17];
    const float* Rw20 = (const float*)d_in[18];
    const float* Rw21 = (const float*)d_in[19];
    const float* Wo0 = (const float*)d_in[20];
    const float* Wo1 = (const float*)d_in[21];
    const float* F0w1 = (const float*)d_in[22];
    const float* F0w2 = (const float*)d_in[23];
    const float* F1w1 = (const float*)d_in[24];
    const float* F1w2 = (const float*)d_in[25];
    float* out = (float*)d_out;

    cudaFuncSetAttribute(attn_kernel, cudaFuncAttributeMaxDynamicSharedMemorySize, ATT_SMEM);

    geom_kernel<<<(NN * Kc + 255) / 256, 256>>>(coords, nbr);
    prenorm_q_init_kernel<<<NN / NB, 256>>>(f0, f1, Wq0, Wq1);

    for (int l = 0; l < 2; l++) {
        node_pre_kernel<<<NN / NB, 256>>>(
            Wk00 + l * 4096, Wk10 + l * 1024,
            Wk01 + l * 1024, Wk11 + l * 256, Wk11r + l * 256,
            Wv00 + l * 4096, Wv10 + l * 1024,
            Wv01 + l * 1024, Wv11 + l * 256, Wv11r + l * 256);
        attn_kernel<<<NN, 256, ATT_SMEM>>>(
            nbr,
            Rw1 + l * 16, Rb1 + l * 16,
            Rw20 + l * 1024, Rw21 + l * 256,
            Wo0 + l * 4096, Wo1 + l * 256);
        const float* nq0 = (l == 0) ? (Wq0 + 64 * 64) : nullptr;
        const float* nq1 = (l == 0) ? (Wq1 + 16 * 16) : nullptr;
        ff_kernel<<<NN / NB, 256>>>(
            F0w1 + l * 64 * 256, F0w2 + l * 256 * 64,
            F1w1 + l * 16 * 64, F1w2 + l * 64 * 16,
            nq0, nq1);
    }
    concat_kernel<<<(NN * 112 + 255) / 256, 256>>>(out);
}